// round 1
// baseline (speedup 1.0000x reference)
#include <cuda_runtime.h>
#include <cstdint>

// ---------------- problem constants ----------------
#define Bx      2
#define Tt      16
#define Hh      56
#define Ww      56
#define Cc      96
#define HEADS   3
#define HD      32
#define WT      8
#define WH      7
#define WWIN    7
#define STs     4
#define SHs     3
#define SWs     3
#define NTOK    392            // WT*WH*WWIN
#define NWIN    128            // (16/8)*(56/7)*(56/7)
#define BWIN    256            // Bx*NWIN
#define LL      50176          // Tt*Hh*Ww
#define TOK     100352         // Bx*LL
#define HIDDEN  384
#define TABLE   2535           // 15*13*13
#define SCALE   0.1767766952966369f  // 32^-0.5

// ---------------- scratch (device globals: alloc-free rule) ----------------
__device__ float g_hwin[TOK * Cc];        // LN1 + partitioned tokens
__device__ float g_q[BWIN * HEADS * NTOK * HD];
__device__ float g_k[BWIN * HEADS * NTOK * HD];
__device__ float g_v[BWIN * HEADS * NTOK * HD];
__device__ float g_owin[TOK * Cc];        // attention output, window order
__device__ float g_x1[TOK * Cc];          // shortcut + proj (residual 1)
__device__ float g_h2[TOK * Cc];          // LN2 output
__device__ float g_m1[TOK * HIDDEN];      // fc1+gelu output

// Map (window-local index, token-in-window) -> original flat spatial index l.
// Window token lives at rolled coords (t,h,w); original coord = (coord+shift) mod dim.
__device__ __forceinline__ int orig_index(int wloc, int n) {
    int wt = wloc >> 6;            // 0..1
    int wh = (wloc >> 3) & 7;      // 0..7
    int ww = wloc & 7;             // 0..7
    int it = n / 49;
    int r  = n % 49;
    int ih = r / 7;
    int iw = r % 7;
    int t = wt * WT + it;
    int h = wh * WH + ih;
    int w = ww * WWIN + iw;
    int to = (t + STs) & 15;
    int ho = h + SHs; if (ho >= Hh) ho -= Hh;
    int wo = w + SWs; if (wo >= Ww) wo -= Ww;
    return (to * Hh + ho) * Ww + wo;
}

// ---------------- LayerNorm (warp per token). PART = gather via roll+partition ----------------
template<bool PART>
__global__ __launch_bounds__(128) void ln_kernel(const float* __restrict__ x,
                                                 const float* __restrict__ gam,
                                                 const float* __restrict__ bet,
                                                 float* __restrict__ out) {
    int warpId = (blockIdx.x * blockDim.x + threadIdx.x) >> 5;   // token index
    int lane = threadIdx.x & 31;
    const float* src;
    if (PART) {
        int n = warpId % NTOK;
        int wglob = warpId / NTOK;
        int b = wglob >> 7;
        int wloc = wglob & 127;
        int l = orig_index(wloc, n);
        src = x + ((size_t)b * LL + l) * Cc;
    } else {
        src = x + (size_t)warpId * Cc;
    }
    float v0 = src[lane], v1 = src[lane + 32], v2 = src[lane + 64];
    float s = v0 + v1 + v2;
    #pragma unroll
    for (int o = 16; o; o >>= 1) s += __shfl_xor_sync(0xffffffffu, s, o);
    float mean = s * (1.0f / 96.0f);
    float d0 = v0 - mean, d1 = v1 - mean, d2 = v2 - mean;
    float q = d0 * d0 + d1 * d1 + d2 * d2;
    #pragma unroll
    for (int o = 16; o; o >>= 1) q += __shfl_xor_sync(0xffffffffu, q, o);
    float rstd = rsqrtf(q * (1.0f / 96.0f) + 1e-5f);
    float* dst = out + (size_t)warpId * Cc;
    dst[lane]      = d0 * rstd * gam[lane]      + bet[lane];
    dst[lane + 32] = d1 * rstd * gam[lane + 32] + bet[lane + 32];
    dst[lane + 64] = d2 * rstd * gam[lane + 64] + bet[lane + 64];
}

// ---------------- Generic SGEMM: C(M,Ncols) = A(M,K) @ Bw(Ncols,K)^T, fused epilogues ----------------
// Tile 64x32, K-chunk 32, 128 threads, 4x4 micro-tile.
// EPI 0: qkv split+scale -> g_q/g_k/g_v     EPI 1: proj + scatter + residual -> g_x1
// EPI 2: gelu(bias+val) -> Cout             EPI 3: bias+val + g_x1 residual -> Cout
template<int EPI>
__global__ __launch_bounds__(128) void gemm_kernel(const float* __restrict__ A,
                                                   const float* __restrict__ Bw,
                                                   const float* __restrict__ bias,
                                                   const float* __restrict__ res,
                                                   float* __restrict__ Cout,
                                                   int K, int Ncols) {
    __shared__ float As[32][64];
    __shared__ float Bs[32][32];
    int m0 = blockIdx.y * 64;
    int n0 = blockIdx.x * 32;
    int tid = threadIdx.x;

    float acc[4][4];
    #pragma unroll
    for (int i = 0; i < 4; i++)
        #pragma unroll
        for (int j = 0; j < 4; j++) acc[i][j] = 0.0f;

    int aRow = tid & 63, aK = tid >> 6;    // aK in {0,1}
    int bRow = tid & 31, bK = tid >> 5;    // bK in {0..3}
    int ty = tid >> 3, tx = tid & 7;

    for (int k0 = 0; k0 < K; k0 += 32) {
        #pragma unroll
        for (int j = 0; j < 4; j++) {
            int k4 = (aK + j * 2) * 4;
            float4 v = *(const float4*)(A + (size_t)(m0 + aRow) * K + k0 + k4);
            As[k4 + 0][aRow] = v.x; As[k4 + 1][aRow] = v.y;
            As[k4 + 2][aRow] = v.z; As[k4 + 3][aRow] = v.w;
        }
        #pragma unroll
        for (int j = 0; j < 2; j++) {
            int k4 = (bK + j * 4) * 4;
            float4 v = *(const float4*)(Bw + (size_t)(n0 + bRow) * K + k0 + k4);
            Bs[k4 + 0][bRow] = v.x; Bs[k4 + 1][bRow] = v.y;
            Bs[k4 + 2][bRow] = v.z; Bs[k4 + 3][bRow] = v.w;
        }
        __syncthreads();
        #pragma unroll
        for (int k = 0; k < 32; k++) {
            float ar[4], br[4];
            *(float4*)ar = *(const float4*)&As[k][ty * 4];
            *(float4*)br = *(const float4*)&Bs[k][tx * 4];
            #pragma unroll
            for (int i = 0; i < 4; i++)
                #pragma unroll
                for (int j = 0; j < 4; j++) acc[i][j] += ar[i] * br[j];
        }
        __syncthreads();
    }

    #pragma unroll
    for (int i = 0; i < 4; i++) {
        int m = m0 + ty * 4 + i;
        #pragma unroll
        for (int j = 0; j < 4; j++) {
            int col = n0 + tx * 4 + j;
            float val = acc[i][j] + bias[col];
            if (EPI == 0) {          // QKV split
                int w = m / NTOK, n = m % NTOK;
                int part = col / 96;
                int hh = col % 96;
                int head = hh >> 5, d = hh & 31;
                size_t dst = (((size_t)(w * 3 + head)) * NTOK + n) * HD + d;
                if (part == 0)      g_q[dst] = val * SCALE;
                else if (part == 1) g_k[dst] = val;
                else                g_v[dst] = val;
            } else if (EPI == 1) {   // proj + window-reverse scatter + residual
                int w = m / NTOK, n = m % NTOK;
                int b = w >> 7, wloc = w & 127;
                int l = orig_index(wloc, n);
                size_t dst = ((size_t)b * LL + l) * Cc + col;
                g_x1[dst] = res[dst] + val;
            } else if (EPI == 2) {   // fc1 + exact gelu
                float gval = 0.5f * val * (1.0f + erff(val * 0.70710678118654752f));
                Cout[(size_t)m * Ncols + col] = gval;
            } else {                 // fc2 + residual
                size_t dst = (size_t)m * Cc + col;
                Cout[dst] = g_x1[dst] + val;
            }
        }
    }
}

// ---------------- Attention: one block per (window, head) ----------------
// smem: K tile (392x32 f32), V tile, rel_bias column for this head (2535 f32), region ids (392 int)
#define SMEM_ATTN ((2 * NTOK * HD + TABLE) * 4 + NTOK * 4)

__global__ __launch_bounds__(128) void attn_kernel(const float* __restrict__ rel_bias) {
    extern __shared__ float smem[];
    float* sK = smem;
    float* sV = sK + NTOK * HD;
    float* sBias = sV + NTOK * HD;
    int* sRid = (int*)(sBias + TABLE);

    int win = blockIdx.x / HEADS;
    int head = blockIdx.x % HEADS;
    int tid = threadIdx.x;

    const float* Kg = g_k + ((size_t)(win * HEADS + head)) * NTOK * HD;
    const float* Vg = g_v + ((size_t)(win * HEADS + head)) * NTOK * HD;
    const float* Qg = g_q + ((size_t)(win * HEADS + head)) * NTOK * HD;

    // cooperative loads
    for (int i = tid; i < NTOK * HD / 4; i += 128) {
        ((float4*)sK)[i] = ((const float4*)Kg)[i];
        ((float4*)sV)[i] = ((const float4*)Vg)[i];
    }
    for (int i = tid; i < TABLE; i += 128) sBias[i] = rel_bias[i * HEADS + head];

    int wloc = win & 127;
    int wt = wloc >> 6, wh = (wloc >> 3) & 7, ww = wloc & 7;
    int t0 = wt * WT, h0 = wh * WH, w0 = ww * WWIN;
    for (int i = tid; i < NTOK; i += 128) {
        int it = i / 49, r = i % 49, ih = r / 7, iw = r % 7;
        int t = t0 + it, h = h0 + ih, w = w0 + iw;
        int rt = (t < Tt - WT)   ? 0 : ((t < Tt - STs) ? 1 : 2);
        int rh = (h < Hh - WH)   ? 0 : ((h < Hh - SHs) ? 1 : 2);
        int rw = (w < Ww - WWIN) ? 0 : ((w < Ww - SWs) ? 1 : 2);
        sRid[i] = rt * 9 + rh * 3 + rw;
    }
    __syncthreads();

    for (int q = tid; q < NTOK; q += 128) {
        float qv[HD];
        const float4* qp = (const float4*)(Qg + (size_t)q * HD);
        #pragma unroll
        for (int e = 0; e < HD / 4; e++) ((float4*)qv)[e] = qp[e];

        int it1 = q / 49, r = q % 49, ih1 = r / 7, iw1 = r % 7;
        int rid_q = sRid[q];

        float m = -1e30f, s = 0.0f;
        float acc[HD];
        #pragma unroll
        for (int d = 0; d < HD; d++) acc[d] = 0.0f;

        int kk = 0;
        const float* kr = sK;
        const float* vr = sV;
        for (int it2 = 0; it2 < WT; it2++) {
            int dtTerm = (it1 - it2 + WT - 1) * 15;
            for (int ih2 = 0; ih2 < WH; ih2++) {
                int dhTerm = dtTerm + (ih1 - ih2 + WH - 1) * 13;
                for (int iw2 = 0; iw2 < WWIN; iw2++) {
                    float sc = sBias[dhTerm + (iw1 - iw2 + WWIN - 1)];
                    if (sRid[kk] != rid_q) sc -= 100.0f;
                    #pragma unroll
                    for (int e = 0; e < HD / 4; e++) {
                        float4 kv = ((const float4*)kr)[e];
                        sc += qv[e * 4 + 0] * kv.x + qv[e * 4 + 1] * kv.y
                            + qv[e * 4 + 2] * kv.z + qv[e * 4 + 3] * kv.w;
                    }
                    if (sc > m) {
                        float corr = __expf(m - sc);   // first iter: exp(-inf)=0
                        s = s * corr + 1.0f;
                        #pragma unroll
                        for (int d = 0; d < HD; d++) acc[d] = acc[d] * corr + vr[d];
                        m = sc;
                    } else {
                        float p = __expf(sc - m);
                        s += p;
                        #pragma unroll
                        for (int d = 0; d < HD; d++) acc[d] += p * vr[d];
                    }
                    kk++; kr += HD; vr += HD;
                }
            }
        }
        float inv = 1.0f / s;
        float* op = g_owin + ((size_t)(win * NTOK + q)) * Cc + head * HD;
        #pragma unroll
        for (int d = 0; d < HD; d++) op[d] = acc[d] * inv;
    }
}

// ---------------- launch ----------------
extern "C" void kernel_launch(void* const* d_in, const int* in_sizes, int n_in,
                              void* d_out, int out_size) {
    const float* x       = (const float*)d_in[0];
    const float* norm1_g = (const float*)d_in[1];
    const float* norm1_b = (const float*)d_in[2];
    const float* qkv_w   = (const float*)d_in[3];
    const float* qkv_b   = (const float*)d_in[4];
    const float* rel_b   = (const float*)d_in[5];
    const float* proj_w  = (const float*)d_in[6];
    const float* proj_b  = (const float*)d_in[7];
    const float* norm2_g = (const float*)d_in[8];
    const float* norm2_b = (const float*)d_in[9];
    const float* fc1_w   = (const float*)d_in[10];
    const float* fc1_b   = (const float*)d_in[11];
    const float* fc2_w   = (const float*)d_in[12];
    const float* fc2_b   = (const float*)d_in[13];
    float* out = (float*)d_out;

    float *hwin, *owin, *x1, *h2, *m1;
    cudaGetSymbolAddress((void**)&hwin, g_hwin);
    cudaGetSymbolAddress((void**)&owin, g_owin);
    cudaGetSymbolAddress((void**)&x1, g_x1);
    cudaGetSymbolAddress((void**)&h2, g_h2);
    cudaGetSymbolAddress((void**)&m1, g_m1);

    cudaFuncSetAttribute(attn_kernel, cudaFuncAttributeMaxDynamicSharedMemorySize, SMEM_ATTN);

    // 1. LN1 + roll + window partition  (TOK warps)
    ln_kernel<true><<<TOK / 4, 128>>>(x, norm1_g, norm1_b, hwin);
    // 2. QKV gemm: (TOK,96) x (288,96)^T
    gemm_kernel<0><<<dim3(288 / 32, TOK / 64), 128>>>(hwin, qkv_w, qkv_b, nullptr, nullptr, 96, 288);
    // 3. attention per (window, head)
    attn_kernel<<<BWIN * HEADS, 128, SMEM_ATTN>>>(rel_b);
    // 4. proj gemm + window reverse + residual -> g_x1
    gemm_kernel<1><<<dim3(96 / 32, TOK / 64), 128>>>(owin, proj_w, proj_b, x, nullptr, 96, 96);
    // 5. LN2
    ln_kernel<false><<<TOK / 4, 128>>>(x1, norm2_g, norm2_b, h2);
    // 6. fc1 + gelu
    gemm_kernel<2><<<dim3(HIDDEN / 32, TOK / 64), 128>>>(h2, fc1_w, fc1_b, nullptr, m1, 96, HIDDEN);
    // 7. fc2 + residual -> out
    gemm_kernel<3><<<dim3(96 / 32, TOK / 64), 128>>>(m1, fc2_w, fc2_b, nullptr, out, HIDDEN, 96);
}

// round 2
// speedup vs baseline: 1.0592x; 1.0592x over previous
#include <cuda_runtime.h>
#include <cstdint>

// ---------------- problem constants ----------------
#define Bx      2
#define Tt      16
#define Hh      56
#define Ww      56
#define Cc      96
#define HEADS   3
#define HD      32
#define WT      8
#define WH      7
#define WWIN    7
#define STs     4
#define SHs     3
#define SWs     3
#define NTOK    392
#define NWIN    128
#define BWIN    256
#define LL      50176
#define TOK     100352
#define HIDDEN  384
#define TABLE   2535
#define BIAS_USED 384          // max rel-pos index actually used is 378
#define SCALE   0.1767766952966369f

// ---------------- scratch (device globals: alloc-free rule) ----------------
__device__ float g_hwin[TOK * Cc];
__device__ float g_q[BWIN * HEADS * NTOK * HD];
__device__ float g_k[BWIN * HEADS * NTOK * HD];
__device__ float g_v[BWIN * HEADS * NTOK * HD];
__device__ float g_owin[TOK * Cc];
__device__ float g_x1[TOK * Cc];
__device__ float g_h2[TOK * Cc];
__device__ float g_m1[TOK * HIDDEN];

__device__ __forceinline__ int orig_index(int wloc, int n) {
    int wt = wloc >> 6;
    int wh = (wloc >> 3) & 7;
    int ww = wloc & 7;
    int it = n / 49;
    int r  = n % 49;
    int ih = r / 7;
    int iw = r % 7;
    int t = wt * WT + it;
    int h = wh * WH + ih;
    int w = ww * WWIN + iw;
    int to = (t + STs) & 15;
    int ho = h + SHs; if (ho >= Hh) ho -= Hh;
    int wo = w + SWs; if (wo >= Ww) wo -= Ww;
    return (to * Hh + ho) * Ww + wo;
}

// ---------------- LayerNorm (warp per token) ----------------
template<bool PART>
__global__ __launch_bounds__(128) void ln_kernel(const float* __restrict__ x,
                                                 const float* __restrict__ gam,
                                                 const float* __restrict__ bet,
                                                 float* __restrict__ out) {
    int warpId = (blockIdx.x * blockDim.x + threadIdx.x) >> 5;
    int lane = threadIdx.x & 31;
    const float* src;
    if (PART) {
        int n = warpId % NTOK;
        int wglob = warpId / NTOK;
        int b = wglob >> 7;
        int wloc = wglob & 127;
        int l = orig_index(wloc, n);
        src = x + ((size_t)b * LL + l) * Cc;
    } else {
        src = x + (size_t)warpId * Cc;
    }
    float v0 = src[lane], v1 = src[lane + 32], v2 = src[lane + 64];
    float s = v0 + v1 + v2;
    #pragma unroll
    for (int o = 16; o; o >>= 1) s += __shfl_xor_sync(0xffffffffu, s, o);
    float mean = s * (1.0f / 96.0f);
    float d0 = v0 - mean, d1 = v1 - mean, d2 = v2 - mean;
    float q = d0 * d0 + d1 * d1 + d2 * d2;
    #pragma unroll
    for (int o = 16; o; o >>= 1) q += __shfl_xor_sync(0xffffffffu, q, o);
    float rstd = rsqrtf(q * (1.0f / 96.0f) + 1e-5f);
    float* dst = out + (size_t)warpId * Cc;
    dst[lane]      = d0 * rstd * gam[lane]      + bet[lane];
    dst[lane + 32] = d1 * rstd * gam[lane + 32] + bet[lane + 32];
    dst[lane + 64] = d2 * rstd * gam[lane + 64] + bet[lane + 64];
}

// ---------------- tf32 tensor-core GEMM ----------------
// C(M,Ncols) = A(M,K) @ Bw(Ncols,K)^T, tile 128x32x16, 4 warps, mma.m16n8k8.tf32
__device__ __forceinline__ uint32_t f2tf32(float f) {
    uint32_t u;
    asm("cvt.rna.tf32.f32 %0, %1;" : "=r"(u) : "f"(f));
    return u;
}
__device__ __forceinline__ void mma_tf32(float* c, const uint32_t* a, const uint32_t* b) {
    asm volatile(
        "mma.sync.aligned.m16n8k8.row.col.f32.tf32.tf32.f32 "
        "{%0,%1,%2,%3},{%4,%5,%6,%7},{%8,%9},{%0,%1,%2,%3};"
        : "+f"(c[0]), "+f"(c[1]), "+f"(c[2]), "+f"(c[3])
        : "r"(a[0]), "r"(a[1]), "r"(a[2]), "r"(a[3]), "r"(b[0]), "r"(b[1]));
}

// EPI 0: qkv split+scale   EPI 1: proj + scatter + residual -> g_x1
// EPI 2: gelu -> Cout      EPI 3: + g_x1 residual -> Cout
template<int EPI>
__global__ __launch_bounds__(128) void gemm_tc(const float* __restrict__ A,
                                               const float* __restrict__ Bw,
                                               const float* __restrict__ bias,
                                               const float* __restrict__ res,
                                               float* __restrict__ Cout,
                                               int K, int Ncols) {
    __shared__ uint32_t sA[128][18];
    __shared__ uint32_t sB[32][18];
    int m0 = blockIdx.y * 128;
    int n0 = blockIdx.x * 32;
    int tid = threadIdx.x;
    int lane = tid & 31, warp = tid >> 5;
    int g = lane >> 2, tig = lane & 3;

    float acc[2][4][4];
    #pragma unroll
    for (int i = 0; i < 2; i++)
        #pragma unroll
        for (int j = 0; j < 4; j++)
            #pragma unroll
            for (int c = 0; c < 4; c++) acc[i][j][c] = 0.0f;

    int ldRow = tid >> 2;      // 0..31
    int ldCol = (tid & 3) * 4; // 0,4,8,12

    for (int k0 = 0; k0 < K; k0 += 16) {
        #pragma unroll
        for (int p = 0; p < 4; p++) {
            int row = ldRow + p * 32;
            float4 v = *(const float4*)(A + (size_t)(m0 + row) * K + k0 + ldCol);
            sA[row][ldCol + 0] = f2tf32(v.x); sA[row][ldCol + 1] = f2tf32(v.y);
            sA[row][ldCol + 2] = f2tf32(v.z); sA[row][ldCol + 3] = f2tf32(v.w);
        }
        {
            float4 v = *(const float4*)(Bw + (size_t)(n0 + ldRow) * K + k0 + ldCol);
            sB[ldRow][ldCol + 0] = f2tf32(v.x); sB[ldRow][ldCol + 1] = f2tf32(v.y);
            sB[ldRow][ldCol + 2] = f2tf32(v.z); sB[ldRow][ldCol + 3] = f2tf32(v.w);
        }
        __syncthreads();
        #pragma unroll
        for (int kk = 0; kk < 2; kk++) {
            int kb = kk * 8;
            uint32_t a[2][4], b[4][2];
            #pragma unroll
            for (int i = 0; i < 2; i++) {
                int r = warp * 32 + i * 16 + g;
                a[i][0] = sA[r][kb + tig];
                a[i][1] = sA[r + 8][kb + tig];
                a[i][2] = sA[r][kb + tig + 4];
                a[i][3] = sA[r + 8][kb + tig + 4];
            }
            #pragma unroll
            for (int j = 0; j < 4; j++) {
                b[j][0] = sB[j * 8 + g][kb + tig];
                b[j][1] = sB[j * 8 + g][kb + tig + 4];
            }
            #pragma unroll
            for (int i = 0; i < 2; i++)
                #pragma unroll
                for (int j = 0; j < 4; j++) mma_tf32(acc[i][j], a[i], b[j]);
        }
        __syncthreads();
    }

    #pragma unroll
    for (int i = 0; i < 2; i++)
        #pragma unroll
        for (int j = 0; j < 4; j++)
            #pragma unroll
            for (int c = 0; c < 4; c++) {
                int m = m0 + warp * 32 + i * 16 + g + ((c >> 1) << 3);
                int col = n0 + j * 8 + tig * 2 + (c & 1);
                float val = acc[i][j][c] + bias[col];
                if (EPI == 0) {
                    int w = m / NTOK, n = m % NTOK;
                    int part = col / 96;
                    int hh = col % 96;
                    int head = hh >> 5, d = hh & 31;
                    size_t dst = (((size_t)(w * 3 + head)) * NTOK + n) * HD + d;
                    if (part == 0)      g_q[dst] = val * SCALE;
                    else if (part == 1) g_k[dst] = val;
                    else                g_v[dst] = val;
                } else if (EPI == 1) {
                    int w = m / NTOK, n = m % NTOK;
                    int b2 = w >> 7, wloc = w & 127;
                    int l = orig_index(wloc, n);
                    size_t dst = ((size_t)b2 * LL + l) * Cc + col;
                    g_x1[dst] = res[dst] + val;
                } else if (EPI == 2) {
                    float gval = 0.5f * val * (1.0f + erff(val * 0.70710678118654752f));
                    Cout[(size_t)m * Ncols + col] = gval;
                } else {
                    size_t dst = (size_t)m * Cc + col;
                    Cout[dst] = g_x1[dst] + val;
                }
            }
}

// ---------------- Attention: one block (256 thr) per (window, head) ----------------
// smem: K tile (392x32 f32) + bias (384 f32) + region ids. V read via L1 (__ldg broadcast).
#define SMEM_ATTN ((NTOK * HD + BIAS_USED) * 4 + NTOK * 4)

__global__ __launch_bounds__(256) void attn_kernel(const float* __restrict__ rel_bias) {
    extern __shared__ float smem[];
    float* sK = smem;
    float* sBias = sK + NTOK * HD;
    int* sRid = (int*)(sBias + BIAS_USED);

    int win = blockIdx.x / HEADS;
    int head = blockIdx.x % HEADS;
    int tid = threadIdx.x;

    const float* Kg = g_k + ((size_t)(win * HEADS + head)) * NTOK * HD;
    const float* Vg = g_v + ((size_t)(win * HEADS + head)) * NTOK * HD;
    const float* Qg = g_q + ((size_t)(win * HEADS + head)) * NTOK * HD;

    for (int i = tid; i < NTOK * HD / 4; i += 256)
        ((float4*)sK)[i] = ((const float4*)Kg)[i];
    for (int i = tid; i < BIAS_USED; i += 256)
        sBias[i] = rel_bias[i * HEADS + head];

    int wloc = win & 127;
    int wt = wloc >> 6, wh = (wloc >> 3) & 7, ww = wloc & 7;
    int t0 = wt * WT, h0 = wh * WH, w0 = ww * WWIN;
    for (int i = tid; i < NTOK; i += 256) {
        int it = i / 49, r = i % 49, ih = r / 7, iw = r % 7;
        int t = t0 + it, h = h0 + ih, w = w0 + iw;
        int rt = (t < Tt - WT)   ? 0 : ((t < Tt - STs) ? 1 : 2);
        int rh = (h < Hh - WH)   ? 0 : ((h < Hh - SHs) ? 1 : 2);
        int rw = (w < Ww - WWIN) ? 0 : ((w < Ww - SWs) ? 1 : 2);
        sRid[i] = rt * 9 + rh * 3 + rw;
    }
    __syncthreads();

    for (int q = tid; q < NTOK; q += 256) {
        float qv[HD];
        const float4* qp = (const float4*)(Qg + (size_t)q * HD);
        #pragma unroll
        for (int e = 0; e < HD / 4; e++) ((float4*)qv)[e] = qp[e];

        int it1 = q / 49, r = q % 49, ih1 = r / 7, iw1 = r % 7;
        int rid_q = sRid[q];

        float s = 0.0f;
        float acc[HD];
        #pragma unroll
        for (int d = 0; d < HD; d++) acc[d] = 0.0f;

        int kk = 0;
        for (int it2 = 0; it2 < WT; it2++) {
            int dtTerm = (it1 - it2 + WT - 1) * 15;
            for (int ih2 = 0; ih2 < WH; ih2++) {
                int dhTerm = dtTerm + (ih1 - ih2 + WH - 1) * 13;
                #pragma unroll
                for (int iw2 = 0; iw2 < WWIN; iw2++) {
                    const float4* kr = (const float4*)(sK + kk * HD);
                    float p0 = 0.f, p1 = 0.f, p2 = 0.f, p3 = 0.f;
                    #pragma unroll
                    for (int e = 0; e < 8; e += 4) {
                        float4 k0 = kr[e + 0], k1 = kr[e + 1], k2 = kr[e + 2], k3 = kr[e + 3];
                        p0 += qv[(e+0)*4+0]*k0.x + qv[(e+0)*4+1]*k0.y + qv[(e+0)*4+2]*k0.z + qv[(e+0)*4+3]*k0.w;
                        p1 += qv[(e+1)*4+0]*k1.x + qv[(e+1)*4+1]*k1.y + qv[(e+1)*4+2]*k1.z + qv[(e+1)*4+3]*k1.w;
                        p2 += qv[(e+2)*4+0]*k2.x + qv[(e+2)*4+1]*k2.y + qv[(e+2)*4+2]*k2.z + qv[(e+2)*4+3]*k2.w;
                        p3 += qv[(e+3)*4+0]*k3.x + qv[(e+3)*4+1]*k3.y + qv[(e+3)*4+2]*k3.z + qv[(e+3)*4+3]*k3.w;
                    }
                    float sc = sBias[dhTerm + (iw1 - iw2 + WWIN - 1)]
                             + ((p0 + p1) + (p2 + p3));
                    if (sRid[kk] != rid_q) sc -= 100.0f;
                    float p = __expf(sc);   // masked terms underflow to 0
                    s += p;
                    const float4* vp = (const float4*)Vg + kk * 8;
                    #pragma unroll
                    for (int e = 0; e < 8; e++) {
                        float4 vv = __ldg(vp + e);
                        acc[e*4+0] += p * vv.x; acc[e*4+1] += p * vv.y;
                        acc[e*4+2] += p * vv.z; acc[e*4+3] += p * vv.w;
                    }
                    kk++;
                }
            }
        }
        float inv = 1.0f / s;
        float* op = g_owin + ((size_t)(win * NTOK + q)) * Cc + head * HD;
        #pragma unroll
        for (int d = 0; d < HD; d++) op[d] = acc[d] * inv;
    }
}

// ---------------- launch ----------------
extern "C" void kernel_launch(void* const* d_in, const int* in_sizes, int n_in,
                              void* d_out, int out_size) {
    const float* x       = (const float*)d_in[0];
    const float* norm1_g = (const float*)d_in[1];
    const float* norm1_b = (const float*)d_in[2];
    const float* qkv_w   = (const float*)d_in[3];
    const float* qkv_b   = (const float*)d_in[4];
    const float* rel_b   = (const float*)d_in[5];
    const float* proj_w  = (const float*)d_in[6];
    const float* proj_b  = (const float*)d_in[7];
    const float* norm2_g = (const float*)d_in[8];
    const float* norm2_b = (const float*)d_in[9];
    const float* fc1_w   = (const float*)d_in[10];
    const float* fc1_b   = (const float*)d_in[11];
    const float* fc2_w   = (const float*)d_in[12];
    const float* fc2_b   = (const float*)d_in[13];
    float* out = (float*)d_out;

    float *hwin, *owin, *x1, *h2, *m1;
    cudaGetSymbolAddress((void**)&hwin, g_hwin);
    cudaGetSymbolAddress((void**)&owin, g_owin);
    cudaGetSymbolAddress((void**)&x1, g_x1);
    cudaGetSymbolAddress((void**)&h2, g_h2);
    cudaGetSymbolAddress((void**)&m1, g_m1);

    cudaFuncSetAttribute(attn_kernel, cudaFuncAttributeMaxDynamicSharedMemorySize, SMEM_ATTN);

    // 1. LN1 + roll + window partition
    ln_kernel<true><<<TOK / 4, 128>>>(x, norm1_g, norm1_b, hwin);
    // 2. QKV gemm (tensor core tf32)
    gemm_tc<0><<<dim3(288 / 32, TOK / 128), 128>>>(hwin, qkv_w, qkv_b, nullptr, nullptr, 96, 288);
    // 3. attention
    attn_kernel<<<BWIN * HEADS, 256, SMEM_ATTN>>>(rel_b);
    // 4. proj gemm + window reverse + residual
    gemm_tc<1><<<dim3(96 / 32, TOK / 128), 128>>>(owin, proj_w, proj_b, x, nullptr, 96, 96);
    // 5. LN2
    ln_kernel<false><<<TOK / 4, 128>>>(x1, norm2_g, norm2_b, h2);
    // 6. fc1 + gelu
    gemm_tc<2><<<dim3(HIDDEN / 32, TOK / 128), 128>>>(h2, fc1_w, fc1_b, nullptr, m1, 96, HIDDEN);
    // 7. fc2 + residual
    gemm_tc<3><<<dim3(96 / 32, TOK / 128), 128>>>(m1, fc2_w, fc2_b, nullptr, out, HIDDEN, 96);
}

// round 3
// speedup vs baseline: 2.4916x; 2.3524x over previous
#include <cuda_runtime.h>
#include <cstdint>

// ---------------- problem constants ----------------
#define Bx      2
#define Tt      16
#define Hh      56
#define Ww      56
#define Cc      96
#define HEADS   3
#define HD      32
#define WT      8
#define WH      7
#define WWIN    7
#define STs     4
#define SHs     3
#define SWs     3
#define NTOK    392
#define NWIN    128
#define BWIN    256
#define LL      50176
#define TOK     100352
#define HIDDEN  384
#define SCALE   0.1767766952966369f

#define TBL_ROWSTRIDE 392
#define TBL_CLS_STRIDE 156800   // 400*392 (8 pad rows)
#define TBL_ENTRIES (24 * 392 * 392)

// ---------------- scratch ----------------
__device__ float g_hwin[TOK * Cc];
__device__ float g_q[BWIN * HEADS * NTOK * HD + 256];   // +8 rows pad for m-tile 24
__device__ float g_k[BWIN * HEADS * NTOK * HD];
__device__ float g_v[BWIN * HEADS * NTOK * HD];
__device__ float g_owin[TOK * Cc];
__device__ float g_x1[TOK * Cc];
__device__ float g_h2[TOK * Cc];
__device__ float g_m1[TOK * HIDDEN];
__device__ float g_tbl[24 * TBL_CLS_STRIDE];            // bias+mask logit table

__device__ __forceinline__ int orig_index(int wloc, int n) {
    int wt = wloc >> 6;
    int wh = (wloc >> 3) & 7;
    int ww = wloc & 7;
    int it = n / 49;
    int r  = n % 49;
    int ih = r / 7;
    int iw = r % 7;
    int t = wt * WT + it;
    int h = wh * WH + ih;
    int w = ww * WWIN + iw;
    int to = (t + STs) & 15;
    int ho = h + SHs; if (ho >= Hh) ho -= Hh;
    int wo = w + SWs; if (wo >= Ww) wo -= Ww;
    return (to * Hh + ho) * Ww + wo;
}

// ---------------- bias+mask table: tbl[cls3][q][k] ----------------
__global__ __launch_bounds__(256) void tbl_kernel(const float* __restrict__ rel_bias) {
    int idx = blockIdx.x * 256 + threadIdx.x;
    if (idx >= TBL_ENTRIES) return;
    int k = idx % 392;
    int t2 = idx / 392;
    int q = t2 % 392;
    int cls3 = t2 / 392;
    int head = cls3 % 3, cls = cls3 / 3;
    int it1 = q / 49, r1 = q % 49, ih1 = r1 / 7, iw1 = r1 % 7;
    int it2 = k / 49, r2 = k % 49, ih2 = r2 / 7, iw2 = r2 % 7;
    float b = rel_bias[((it1 - it2 + 7) * 15 + (ih1 - ih2 + 6) * 13 + (iw1 - iw2 + 6)) * 3 + head];
    int bt = (cls >> 2) & 1, bh = (cls >> 1) & 1, bw = cls & 1;
    int rt1 = bt ? (it1 < 4 ? 1 : 2) : 0, rt2 = bt ? (it2 < 4 ? 1 : 2) : 0;
    int rh1 = bh ? (ih1 < 4 ? 1 : 2) : 0, rh2 = bh ? (ih2 < 4 ? 1 : 2) : 0;
    int rw1 = bw ? (iw1 < 4 ? 1 : 2) : 0, rw2 = bw ? (iw2 < 4 ? 1 : 2) : 0;
    if (rt1 != rt2 || rh1 != rh2 || rw1 != rw2) b -= 100.0f;
    g_tbl[cls3 * TBL_CLS_STRIDE + q * TBL_ROWSTRIDE + k] = b;
}

// ---------------- LayerNorm ----------------
template<bool PART>
__global__ __launch_bounds__(128) void ln_kernel(const float* __restrict__ x,
                                                 const float* __restrict__ gam,
                                                 const float* __restrict__ bet,
                                                 float* __restrict__ out) {
    int warpId = (blockIdx.x * blockDim.x + threadIdx.x) >> 5;
    int lane = threadIdx.x & 31;
    const float* src;
    if (PART) {
        int n = warpId % NTOK;
        int wglob = warpId / NTOK;
        int b = wglob >> 7;
        int wloc = wglob & 127;
        int l = orig_index(wloc, n);
        src = x + ((size_t)b * LL + l) * Cc;
    } else {
        src = x + (size_t)warpId * Cc;
    }
    float v0 = src[lane], v1 = src[lane + 32], v2 = src[lane + 64];
    float s = v0 + v1 + v2;
    #pragma unroll
    for (int o = 16; o; o >>= 1) s += __shfl_xor_sync(0xffffffffu, s, o);
    float mean = s * (1.0f / 96.0f);
    float d0 = v0 - mean, d1 = v1 - mean, d2 = v2 - mean;
    float q = d0 * d0 + d1 * d1 + d2 * d2;
    #pragma unroll
    for (int o = 16; o; o >>= 1) q += __shfl_xor_sync(0xffffffffu, q, o);
    float rstd = rsqrtf(q * (1.0f / 96.0f) + 1e-5f);
    float* dst = out + (size_t)warpId * Cc;
    dst[lane]      = d0 * rstd * gam[lane]      + bet[lane];
    dst[lane + 32] = d1 * rstd * gam[lane + 32] + bet[lane + 32];
    dst[lane + 64] = d2 * rstd * gam[lane + 64] + bet[lane + 64];
}

// ---------------- tf32 helpers ----------------
__device__ __forceinline__ uint32_t f2tf32(float f) {
    uint32_t u;
    asm("cvt.rna.tf32.f32 %0, %1;" : "=r"(u) : "f"(f));
    return u;
}
__device__ __forceinline__ void mma_tf32(float* c, const uint32_t* a, const uint32_t* b) {
    asm volatile(
        "mma.sync.aligned.m16n8k8.row.col.f32.tf32.tf32.f32 "
        "{%0,%1,%2,%3},{%4,%5,%6,%7},{%8,%9},{%0,%1,%2,%3};"
        : "+f"(c[0]), "+f"(c[1]), "+f"(c[2]), "+f"(c[3])
        : "r"(a[0]), "r"(a[1]), "r"(a[2]), "r"(a[3]), "r"(b[0]), "r"(b[1]));
}

// ---------------- tf32 tensor-core GEMM (unchanged from R2) ----------------
template<int EPI>
__global__ __launch_bounds__(128) void gemm_tc(const float* __restrict__ A,
                                               const float* __restrict__ Bw,
                                               const float* __restrict__ bias,
                                               const float* __restrict__ res,
                                               float* __restrict__ Cout,
                                               int K, int Ncols) {
    __shared__ uint32_t sA[128][18];
    __shared__ uint32_t sB[32][18];
    int m0 = blockIdx.y * 128;
    int n0 = blockIdx.x * 32;
    int tid = threadIdx.x;
    int lane = tid & 31, warp = tid >> 5;
    int g = lane >> 2, tig = lane & 3;

    float acc[2][4][4];
    #pragma unroll
    for (int i = 0; i < 2; i++)
        #pragma unroll
        for (int j = 0; j < 4; j++)
            #pragma unroll
            for (int c = 0; c < 4; c++) acc[i][j][c] = 0.0f;

    int ldRow = tid >> 2;
    int ldCol = (tid & 3) * 4;

    for (int k0 = 0; k0 < K; k0 += 16) {
        #pragma unroll
        for (int p = 0; p < 4; p++) {
            int row = ldRow + p * 32;
            float4 v = *(const float4*)(A + (size_t)(m0 + row) * K + k0 + ldCol);
            sA[row][ldCol + 0] = f2tf32(v.x); sA[row][ldCol + 1] = f2tf32(v.y);
            sA[row][ldCol + 2] = f2tf32(v.z); sA[row][ldCol + 3] = f2tf32(v.w);
        }
        {
            float4 v = *(const float4*)(Bw + (size_t)(n0 + ldRow) * K + k0 + ldCol);
            sB[ldRow][ldCol + 0] = f2tf32(v.x); sB[ldRow][ldCol + 1] = f2tf32(v.y);
            sB[ldRow][ldCol + 2] = f2tf32(v.z); sB[ldRow][ldCol + 3] = f2tf32(v.w);
        }
        __syncthreads();
        #pragma unroll
        for (int kk = 0; kk < 2; kk++) {
            int kb = kk * 8;
            uint32_t a[2][4], b[4][2];
            #pragma unroll
            for (int i = 0; i < 2; i++) {
                int r = warp * 32 + i * 16 + g;
                a[i][0] = sA[r][kb + tig];
                a[i][1] = sA[r + 8][kb + tig];
                a[i][2] = sA[r][kb + tig + 4];
                a[i][3] = sA[r + 8][kb + tig + 4];
            }
            #pragma unroll
            for (int j = 0; j < 4; j++) {
                b[j][0] = sB[j * 8 + g][kb + tig];
                b[j][1] = sB[j * 8 + g][kb + tig + 4];
            }
            #pragma unroll
            for (int i = 0; i < 2; i++)
                #pragma unroll
                for (int j = 0; j < 4; j++) mma_tf32(acc[i][j], a[i], b[j]);
        }
        __syncthreads();
    }

    #pragma unroll
    for (int i = 0; i < 2; i++)
        #pragma unroll
        for (int j = 0; j < 4; j++)
            #pragma unroll
            for (int c = 0; c < 4; c++) {
                int m = m0 + warp * 32 + i * 16 + g + ((c >> 1) << 3);
                int col = n0 + j * 8 + tig * 2 + (c & 1);
                float val = acc[i][j][c] + bias[col];
                if (EPI == 0) {
                    int w = m / NTOK, n = m % NTOK;
                    int part = col / 96;
                    int hh = col % 96;
                    int head = hh >> 5, d = hh & 31;
                    size_t dst = (((size_t)(w * 3 + head)) * NTOK + n) * HD + d;
                    if (part == 0)      g_q[dst] = val * SCALE;
                    else if (part == 1) g_k[dst] = val;
                    else                g_v[dst] = val;
                } else if (EPI == 1) {
                    int w = m / NTOK, n = m % NTOK;
                    int b2 = w >> 7, wloc = w & 127;
                    int l = orig_index(wloc, n);
                    size_t dst = ((size_t)b2 * LL + l) * Cc + col;
                    g_x1[dst] = res[dst] + val;
                } else if (EPI == 2) {
                    float gval = 0.5f * val * (1.0f + erff(val * 0.70710678118654752f));
                    Cout[(size_t)m * Ncols + col] = gval;
                } else {
                    size_t dst = (size_t)m * Cc + col;
                    Cout[dst] = g_x1[dst] + val;
                }
            }
}

// ---------------- MMA attention ----------------
// One block (8 warps, 256 thr) per (window, head).
// smem: sK [392][36] tf32 | sVT [32][404] tf32 | sP per-warp [16][60] tf32
#define SK_STR   36
#define SVT_STR  404
#define SP_STR   60
#define SK_OFF   0
#define SVT_OFF  (392 * SK_STR)                 // 14112
#define SP_OFF   (SVT_OFF + 32 * SVT_STR)       // 27040
#define SMEM_ATTN ((SP_OFF + 8 * 16 * SP_STR) * 4)   // 138,880 B

__global__ __launch_bounds__(256) void attn_mma_kernel() {
    extern __shared__ uint32_t smem[];
    uint32_t* sK  = smem + SK_OFF;
    uint32_t* sVT = smem + SVT_OFF;

    int win  = blockIdx.x / HEADS;
    int head = blockIdx.x % HEADS;
    int tid  = threadIdx.x;
    int lane = tid & 31, warp = tid >> 5;
    int g = lane >> 2, tig = lane & 3;
    uint32_t* sP = smem + SP_OFF + warp * (16 * SP_STR);

    const float* Kg = g_k + ((size_t)(win * HEADS + head)) * NTOK * HD;
    const float* Vg = g_v + ((size_t)(win * HEADS + head)) * NTOK * HD;
    const float* Qg = g_q + ((size_t)(win * HEADS + head)) * NTOK * HD;

    // table base for this block's mask class
    int wloc = win & 127;
    int wt = wloc >> 6, wh = (wloc >> 3) & 7, ww = wloc & 7;
    int cls = ((wt == 1) << 2) | ((wh == 7) << 1) | (ww == 7);
    const float* tbl = g_tbl + (size_t)(cls * 3 + head) * TBL_CLS_STRIDE;

    // load K (row-major) and V^T into smem as tf32
    for (int i = tid; i < NTOK * 8; i += 256) {
        float4 kv = ((const float4*)Kg)[i];
        int row = i >> 3, c = (i & 7) << 2;
        uint32_t* d = sK + row * SK_STR + c;
        d[0] = f2tf32(kv.x); d[1] = f2tf32(kv.y); d[2] = f2tf32(kv.z); d[3] = f2tf32(kv.w);
        float4 vv = ((const float4*)Vg)[i];
        sVT[(c + 0) * SVT_STR + row] = f2tf32(vv.x);
        sVT[(c + 1) * SVT_STR + row] = f2tf32(vv.y);
        sVT[(c + 2) * SVT_STR + row] = f2tf32(vv.z);
        sVT[(c + 3) * SVT_STR + row] = f2tf32(vv.w);
    }
    __syncthreads();

    // m-tiles of 16 q rows; 25 tiles over 8 warps
    for (int mt = warp; mt < 25; mt += 8) {
        int row0 = mt * 16 + g;          // this thread's base q row
        // Q fragments (reused for all key chunks)
        uint32_t aq[4][4];
        const float* Qr = Qg + row0 * HD;
        #pragma unroll
        for (int ks = 0; ks < 4; ks++) {
            aq[ks][0] = f2tf32(__ldg(Qr + ks * 8 + tig));
            aq[ks][1] = f2tf32(__ldg(Qr + 256 + ks * 8 + tig));
            aq[ks][2] = f2tf32(__ldg(Qr + ks * 8 + tig + 4));
            aq[ks][3] = f2tf32(__ldg(Qr + 256 + ks * 8 + tig + 4));
        }

        float o[4][4];
        #pragma unroll
        for (int nf = 0; nf < 4; nf++)
            #pragma unroll
            for (int e = 0; e < 4; e++) o[nf][e] = 0.0f;
        float sum0 = 0.0f, sum1 = 0.0f;

        for (int c = 0; c < 7; c++) {            // 7 key chunks of 56
            int n0 = c * 56;
            float s[7][4];
            #pragma unroll
            for (int j = 0; j < 7; j++)
                #pragma unroll
                for (int e = 0; e < 4; e++) s[j][e] = 0.0f;
            #pragma unroll
            for (int ks = 0; ks < 4; ks++) {
                #pragma unroll
                for (int j = 0; j < 7; j++) {
                    uint32_t b[2];
                    const uint32_t* kb = sK + (n0 + j * 8 + g) * SK_STR + ks * 8 + tig;
                    b[0] = kb[0]; b[1] = kb[4];
                    mma_tf32(s[j], aq[ks], b);
                }
            }
            // epilogue: add table, exp, accumulate row sums, stage P
            __syncwarp();
            #pragma unroll
            for (int j = 0; j < 7; j++) {
                int colBase = n0 + j * 8 + tig * 2;
                float2 t0 = *(const float2*)(tbl + (size_t)row0 * TBL_ROWSTRIDE + colBase);
                float2 t1 = *(const float2*)(tbl + (size_t)(row0 + 8) * TBL_ROWSTRIDE + colBase);
                float p0 = __expf(s[j][0] + t0.x);
                float p1 = __expf(s[j][1] + t0.y);
                float p2 = __expf(s[j][2] + t1.x);
                float p3 = __expf(s[j][3] + t1.y);
                sum0 += p0 + p1;
                sum1 += p2 + p3;
                int lc = j * 8 + tig * 2;
                sP[g * SP_STR + lc]           = f2tf32(p0);
                sP[g * SP_STR + lc + 1]       = f2tf32(p1);
                sP[(g + 8) * SP_STR + lc]     = f2tf32(p2);
                sP[(g + 8) * SP_STR + lc + 1] = f2tf32(p3);
            }
            __syncwarp();
            // O += P @ V  (k = 56 -> 7 ksteps)
            #pragma unroll
            for (int ks = 0; ks < 7; ks++) {
                uint32_t ap[4];
                ap[0] = sP[g * SP_STR + ks * 8 + tig];
                ap[1] = sP[(g + 8) * SP_STR + ks * 8 + tig];
                ap[2] = sP[g * SP_STR + ks * 8 + tig + 4];
                ap[3] = sP[(g + 8) * SP_STR + ks * 8 + tig + 4];
                #pragma unroll
                for (int nf = 0; nf < 4; nf++) {
                    uint32_t b[2];
                    const uint32_t* vb = sVT + (nf * 8 + g) * SVT_STR + n0 + ks * 8 + tig;
                    b[0] = vb[0]; b[1] = vb[4];
                    mma_tf32(o[nf], ap, b);
                }
            }
        }

        // reduce row sums across the quad (lanes sharing g)
        sum0 += __shfl_xor_sync(0xffffffffu, sum0, 1);
        sum0 += __shfl_xor_sync(0xffffffffu, sum0, 2);
        sum1 += __shfl_xor_sync(0xffffffffu, sum1, 1);
        sum1 += __shfl_xor_sync(0xffffffffu, sum1, 2);
        float inv0 = 1.0f / sum0, inv1 = 1.0f / sum1;

        // store O
        #pragma unroll
        for (int nf = 0; nf < 4; nf++) {
            int col = head * HD + nf * 8 + tig * 2;
            if (row0 < NTOK) {
                float2 v; v.x = o[nf][0] * inv0; v.y = o[nf][1] * inv0;
                *(float2*)(g_owin + ((size_t)(win * NTOK + row0)) * Cc + col) = v;
            }
            if (row0 + 8 < NTOK) {
                float2 v; v.x = o[nf][2] * inv1; v.y = o[nf][3] * inv1;
                *(float2*)(g_owin + ((size_t)(win * NTOK + row0 + 8)) * Cc + col) = v;
            }
        }
    }
}

// ---------------- launch ----------------
extern "C" void kernel_launch(void* const* d_in, const int* in_sizes, int n_in,
                              void* d_out, int out_size) {
    const float* x       = (const float*)d_in[0];
    const float* norm1_g = (const float*)d_in[1];
    const float* norm1_b = (const float*)d_in[2];
    const float* qkv_w   = (const float*)d_in[3];
    const float* qkv_b   = (const float*)d_in[4];
    const float* rel_b   = (const float*)d_in[5];
    const float* proj_w  = (const float*)d_in[6];
    const float* proj_b  = (const float*)d_in[7];
    const float* norm2_g = (const float*)d_in[8];
    const float* norm2_b = (const float*)d_in[9];
    const float* fc1_w   = (const float*)d_in[10];
    const float* fc1_b   = (const float*)d_in[11];
    const float* fc2_w   = (const float*)d_in[12];
    const float* fc2_b   = (const float*)d_in[13];
    float* out = (float*)d_out;

    float *hwin, *owin, *x1, *h2, *m1;
    cudaGetSymbolAddress((void**)&hwin, g_hwin);
    cudaGetSymbolAddress((void**)&owin, g_owin);
    cudaGetSymbolAddress((void**)&x1, g_x1);
    cudaGetSymbolAddress((void**)&h2, g_h2);
    cudaGetSymbolAddress((void**)&m1, g_m1);

    cudaFuncSetAttribute(attn_mma_kernel, cudaFuncAttributeMaxDynamicSharedMemorySize, SMEM_ATTN);

    // 0. bias+mask table (only needs rel_bias)
    tbl_kernel<<<(TBL_ENTRIES + 255) / 256, 256>>>(rel_b);
    // 1. LN1 + roll + window partition
    ln_kernel<true><<<TOK / 4, 128>>>(x, norm1_g, norm1_b, hwin);
    // 2. QKV gemm
    gemm_tc<0><<<dim3(288 / 32, TOK / 128), 128>>>(hwin, qkv_w, qkv_b, nullptr, nullptr, 96, 288);
    // 3. attention (tensor core)
    attn_mma_kernel<<<BWIN * HEADS, 256, SMEM_ATTN>>>();
    // 4. proj + window reverse + residual
    gemm_tc<1><<<dim3(96 / 32, TOK / 128), 128>>>(owin, proj_w, proj_b, x, nullptr, 96, 96);
    // 5. LN2
    ln_kernel<false><<<TOK / 4, 128>>>(x1, norm2_g, norm2_b, h2);
    // 6. fc1 + gelu
    gemm_tc<2><<<dim3(HIDDEN / 32, TOK / 128), 128>>>(h2, fc1_w, fc1_b, nullptr, m1, 96, HIDDEN);
    // 7. fc2 + residual
    gemm_tc<3><<<dim3(96 / 32, TOK / 128), 128>>>(m1, fc2_w, fc2_b, nullptr, out, HIDDEN, 96);
}

// round 4
// speedup vs baseline: 2.9974x; 1.2030x over previous
#include <cuda_runtime.h>
#include <cstdint>

// ---------------- problem constants ----------------
#define Bx      2
#define Tt      16
#define Hh      56
#define Ww      56
#define Cc      96
#define HEADS   3
#define HD      32
#define WT      8
#define WH      7
#define WWIN    7
#define STs     4
#define SHs     3
#define SWs     3
#define NTOK    392
#define NWIN    128
#define BWIN    256
#define LL      50176
#define TOK     100352
#define HIDDEN  384
#define SCALE   0.1767766952966369f

#define TBL_ROWSTRIDE 392
#define TBL_CLS_STRIDE 156800   // 400*392 (8 pad rows)
#define TBL_ENTRIES (24 * 392 * 392)

// ---------------- scratch ----------------
__device__ float g_hwin[TOK * Cc];
__device__ float g_q[BWIN * HEADS * NTOK * HD + 256];   // +8 rows pad for m-tile 24
__device__ float g_k[BWIN * HEADS * NTOK * HD];
__device__ float g_v[BWIN * HEADS * NTOK * HD];
__device__ float g_owin[TOK * Cc];
__device__ float g_x1[TOK * Cc];
__device__ float g_h2[TOK * Cc];
__device__ float g_m1[TOK * HIDDEN];
__device__ float g_tbl[24 * TBL_CLS_STRIDE];            // bias+mask logit table

__device__ __forceinline__ int orig_index(int wloc, int n) {
    int wt = wloc >> 6;
    int wh = (wloc >> 3) & 7;
    int ww = wloc & 7;
    int it = n / 49;
    int r  = n % 49;
    int ih = r / 7;
    int iw = r % 7;
    int t = wt * WT + it;
    int h = wh * WH + ih;
    int w = ww * WWIN + iw;
    int to = (t + STs) & 15;
    int ho = h + SHs; if (ho >= Hh) ho -= Hh;
    int wo = w + SWs; if (wo >= Ww) wo -= Ww;
    return (to * Hh + ho) * Ww + wo;
}

// ---------------- bias+mask table ----------------
__global__ __launch_bounds__(256) void tbl_kernel(const float* __restrict__ rel_bias) {
    int idx = blockIdx.x * 256 + threadIdx.x;
    if (idx >= TBL_ENTRIES) return;
    int k = idx % 392;
    int t2 = idx / 392;
    int q = t2 % 392;
    int cls3 = t2 / 392;
    int head = cls3 % 3, cls = cls3 / 3;
    int it1 = q / 49, r1 = q % 49, ih1 = r1 / 7, iw1 = r1 % 7;
    int it2 = k / 49, r2 = k % 49, ih2 = r2 / 7, iw2 = r2 % 7;
    float b = rel_bias[((it1 - it2 + 7) * 15 + (ih1 - ih2 + 6) * 13 + (iw1 - iw2 + 6)) * 3 + head];
    int bt = (cls >> 2) & 1, bh = (cls >> 1) & 1, bw = cls & 1;
    int rt1 = bt ? (it1 < 4 ? 1 : 2) : 0, rt2 = bt ? (it2 < 4 ? 1 : 2) : 0;
    int rh1 = bh ? (ih1 < 4 ? 1 : 2) : 0, rh2 = bh ? (ih2 < 4 ? 1 : 2) : 0;
    int rw1 = bw ? (iw1 < 4 ? 1 : 2) : 0, rw2 = bw ? (iw2 < 4 ? 1 : 2) : 0;
    if (rt1 != rt2 || rh1 != rh2 || rw1 != rw2) b -= 100.0f;
    g_tbl[cls3 * TBL_CLS_STRIDE + q * TBL_ROWSTRIDE + k] = b;
}

// ---------------- LayerNorm ----------------
template<bool PART>
__global__ __launch_bounds__(128) void ln_kernel(const float* __restrict__ x,
                                                 const float* __restrict__ gam,
                                                 const float* __restrict__ bet,
                                                 float* __restrict__ out) {
    int warpId = (blockIdx.x * blockDim.x + threadIdx.x) >> 5;
    int lane = threadIdx.x & 31;
    const float* src;
    if (PART) {
        int n = warpId % NTOK;
        int wglob = warpId / NTOK;
        int b = wglob >> 7;
        int wloc = wglob & 127;
        int l = orig_index(wloc, n);
        src = x + ((size_t)b * LL + l) * Cc;
    } else {
        src = x + (size_t)warpId * Cc;
    }
    float v0 = src[lane], v1 = src[lane + 32], v2 = src[lane + 64];
    float s = v0 + v1 + v2;
    #pragma unroll
    for (int o = 16; o; o >>= 1) s += __shfl_xor_sync(0xffffffffu, s, o);
    float mean = s * (1.0f / 96.0f);
    float d0 = v0 - mean, d1 = v1 - mean, d2 = v2 - mean;
    float q = d0 * d0 + d1 * d1 + d2 * d2;
    #pragma unroll
    for (int o = 16; o; o >>= 1) q += __shfl_xor_sync(0xffffffffu, q, o);
    float rstd = rsqrtf(q * (1.0f / 96.0f) + 1e-5f);
    float* dst = out + (size_t)warpId * Cc;
    dst[lane]      = d0 * rstd * gam[lane]      + bet[lane];
    dst[lane + 32] = d1 * rstd * gam[lane + 32] + bet[lane + 32];
    dst[lane + 64] = d2 * rstd * gam[lane + 64] + bet[lane + 64];
}

// ---------------- tf32 helpers ----------------
__device__ __forceinline__ uint32_t f2tf32(float f) {
    uint32_t u;
    asm("cvt.rna.tf32.f32 %0, %1;" : "=r"(u) : "f"(f));
    return u;
}
__device__ __forceinline__ void mma_tf32(float* c, const uint32_t* a, const uint32_t* b) {
    asm volatile(
        "mma.sync.aligned.m16n8k8.row.col.f32.tf32.tf32.f32 "
        "{%0,%1,%2,%3},{%4,%5,%6,%7},{%8,%9},{%0,%1,%2,%3};"
        : "+f"(c[0]), "+f"(c[1]), "+f"(c[2]), "+f"(c[3])
        : "r"(a[0]), "r"(a[1]), "r"(a[2]), "r"(a[3]), "r"(b[0]), "r"(b[1]));
}

// ---------------- tf32 GEMM with register prefetch pipeline ----------------
template<int EPI>
__global__ __launch_bounds__(128) void gemm_tc(const float* __restrict__ A,
                                               const float* __restrict__ Bw,
                                               const float* __restrict__ bias,
                                               const float* __restrict__ res,
                                               float* __restrict__ Cout,
                                               int K, int Ncols) {
    __shared__ uint32_t sA[128][18];
    __shared__ uint32_t sB[32][18];
    int m0 = blockIdx.y * 128;
    int n0 = blockIdx.x * 32;
    int tid = threadIdx.x;
    int lane = tid & 31, warp = tid >> 5;
    int g = lane >> 2, tig = lane & 3;

    float acc[2][4][4];
    #pragma unroll
    for (int i = 0; i < 2; i++)
        #pragma unroll
        for (int j = 0; j < 4; j++)
            #pragma unroll
            for (int c = 0; c < 4; c++) acc[i][j][c] = 0.0f;

    int ldRow = tid >> 2;
    int ldCol = (tid & 3) * 4;

    float4 ra[4], rb;
    #pragma unroll
    for (int p = 0; p < 4; p++)
        ra[p] = *(const float4*)(A + (size_t)(m0 + ldRow + p * 32) * K + ldCol);
    rb = *(const float4*)(Bw + (size_t)(n0 + ldRow) * K + ldCol);

    for (int k0 = 0; k0 < K; k0 += 16) {
        #pragma unroll
        for (int p = 0; p < 4; p++) {
            int row = ldRow + p * 32;
            sA[row][ldCol + 0] = f2tf32(ra[p].x); sA[row][ldCol + 1] = f2tf32(ra[p].y);
            sA[row][ldCol + 2] = f2tf32(ra[p].z); sA[row][ldCol + 3] = f2tf32(ra[p].w);
        }
        sB[ldRow][ldCol + 0] = f2tf32(rb.x); sB[ldRow][ldCol + 1] = f2tf32(rb.y);
        sB[ldRow][ldCol + 2] = f2tf32(rb.z); sB[ldRow][ldCol + 3] = f2tf32(rb.w);
        __syncthreads();
        if (k0 + 16 < K) {   // prefetch next chunk (overlaps MMAs below)
            #pragma unroll
            for (int p = 0; p < 4; p++)
                ra[p] = *(const float4*)(A + (size_t)(m0 + ldRow + p * 32) * K + k0 + 16 + ldCol);
            rb = *(const float4*)(Bw + (size_t)(n0 + ldRow) * K + k0 + 16 + ldCol);
        }
        #pragma unroll
        for (int kk = 0; kk < 2; kk++) {
            int kb = kk * 8;
            uint32_t a[2][4], b[4][2];
            #pragma unroll
            for (int i = 0; i < 2; i++) {
                int r = warp * 32 + i * 16 + g;
                a[i][0] = sA[r][kb + tig];
                a[i][1] = sA[r + 8][kb + tig];
                a[i][2] = sA[r][kb + tig + 4];
                a[i][3] = sA[r + 8][kb + tig + 4];
            }
            #pragma unroll
            for (int j = 0; j < 4; j++) {
                b[j][0] = sB[j * 8 + g][kb + tig];
                b[j][1] = sB[j * 8 + g][kb + tig + 4];
            }
            #pragma unroll
            for (int i = 0; i < 2; i++)
                #pragma unroll
                for (int j = 0; j < 4; j++) mma_tf32(acc[i][j], a[i], b[j]);
        }
        __syncthreads();
    }

    #pragma unroll
    for (int i = 0; i < 2; i++)
        #pragma unroll
        for (int j = 0; j < 4; j++)
            #pragma unroll
            for (int c = 0; c < 4; c++) {
                int m = m0 + warp * 32 + i * 16 + g + ((c >> 1) << 3);
                int col = n0 + j * 8 + tig * 2 + (c & 1);
                float val = acc[i][j][c] + bias[col];
                if (EPI == 0) {
                    int w = m / NTOK, n = m % NTOK;
                    int part = col / 96;
                    int hh = col % 96;
                    int head = hh >> 5, d = hh & 31;
                    size_t dst = (((size_t)(w * 3 + head)) * NTOK + n) * HD + d;
                    if (part == 0)      g_q[dst] = val * SCALE;
                    else if (part == 1) g_k[dst] = val;
                    else                g_v[dst] = val;
                } else if (EPI == 1) {
                    int w = m / NTOK, n = m % NTOK;
                    int b2 = w >> 7, wloc = w & 127;
                    int l = orig_index(wloc, n);
                    size_t dst = ((size_t)b2 * LL + l) * Cc + col;
                    g_x1[dst] = res[dst] + val;
                } else if (EPI == 2) {
                    float gval = 0.5f * val * (1.0f + erff(val * 0.70710678118654752f));
                    Cout[(size_t)m * Ncols + col] = gval;
                } else {
                    size_t dst = (size_t)m * Cc + col;
                    Cout[dst] = g_x1[dst] + val;
                }
            }
}

// ---------------- MMA attention (shuffle-P, 2 blocks/SM) ----------------
#define SK_STR   36
#define SVT_STR  404
#define SK_OFF   0
#define SVT_OFF  (392 * SK_STR)                     // 14112
#define SMEM_ATTN ((SVT_OFF + 32 * SVT_STR) * 4)    // 108,160 B

__global__ __launch_bounds__(256, 2) void attn_mma_kernel() {
    extern __shared__ uint32_t smem[];
    uint32_t* sK  = smem + SK_OFF;
    uint32_t* sVT = smem + SVT_OFF;

    int win  = blockIdx.x / HEADS;
    int head = blockIdx.x % HEADS;
    int tid  = threadIdx.x;
    int lane = tid & 31, warp = tid >> 5;
    int g = lane >> 2, tig = lane & 3;

    const float* Kg = g_k + ((size_t)(win * HEADS + head)) * NTOK * HD;
    const float* Vg = g_v + ((size_t)(win * HEADS + head)) * NTOK * HD;
    const float* Qg = g_q + ((size_t)(win * HEADS + head)) * NTOK * HD;

    int wloc = win & 127;
    int wt = wloc >> 6, wh = (wloc >> 3) & 7, ww = wloc & 7;
    int cls = ((wt == 1) << 2) | ((wh == 7) << 1) | (ww == 7);
    const float* tbl = g_tbl + (size_t)(cls * 3 + head) * TBL_CLS_STRIDE;

    for (int i = tid; i < NTOK * 8; i += 256) {
        float4 kv = ((const float4*)Kg)[i];
        int row = i >> 3, c = (i & 7) << 2;
        uint32_t* d = sK + row * SK_STR + c;
        d[0] = f2tf32(kv.x); d[1] = f2tf32(kv.y); d[2] = f2tf32(kv.z); d[3] = f2tf32(kv.w);
        float4 vv = ((const float4*)Vg)[i];
        sVT[(c + 0) * SVT_STR + row] = f2tf32(vv.x);
        sVT[(c + 1) * SVT_STR + row] = f2tf32(vv.y);
        sVT[(c + 2) * SVT_STR + row] = f2tf32(vv.z);
        sVT[(c + 3) * SVT_STR + row] = f2tf32(vv.w);
    }
    __syncthreads();

    int src1 = g * 4 + (tig >> 1);   // quad lane owning col tig
    int src2 = src1 + 2;             // quad lane owning col tig+4
    bool odd = (tig & 1);

    for (int mt = warp; mt < 25; mt += 8) {
        int row0 = mt * 16 + g;
        uint32_t aq[4][4];
        const float* Qr = Qg + row0 * HD;
        #pragma unroll
        for (int ks = 0; ks < 4; ks++) {
            aq[ks][0] = f2tf32(__ldg(Qr + ks * 8 + tig));
            aq[ks][1] = f2tf32(__ldg(Qr + 256 + ks * 8 + tig));
            aq[ks][2] = f2tf32(__ldg(Qr + ks * 8 + tig + 4));
            aq[ks][3] = f2tf32(__ldg(Qr + 256 + ks * 8 + tig + 4));
        }

        float o[4][4];
        #pragma unroll
        for (int nf = 0; nf < 4; nf++)
            #pragma unroll
            for (int e = 0; e < 4; e++) o[nf][e] = 0.0f;
        float sum0 = 0.0f, sum1 = 0.0f;

        for (int c = 0; c < 7; c++) {
            int n0 = c * 56;
            float s[7][4];
            #pragma unroll
            for (int j = 0; j < 7; j++)
                #pragma unroll
                for (int e = 0; e < 4; e++) s[j][e] = 0.0f;
            #pragma unroll
            for (int ks = 0; ks < 4; ks++) {
                #pragma unroll
                for (int j = 0; j < 7; j++) {
                    uint32_t b[2];
                    const uint32_t* kb = sK + (n0 + j * 8 + g) * SK_STR + ks * 8 + tig;
                    b[0] = kb[0]; b[1] = kb[4];
                    mma_tf32(s[j], aq[ks], b);
                }
            }
            // softmax numerators (no max-sub; logits bounded, mask underflows to 0)
            #pragma unroll
            for (int j = 0; j < 7; j++) {
                int colBase = n0 + j * 8 + tig * 2;
                float2 t0 = *(const float2*)(tbl + (size_t)row0 * TBL_ROWSTRIDE + colBase);
                float2 t1 = *(const float2*)(tbl + (size_t)(row0 + 8) * TBL_ROWSTRIDE + colBase);
                s[j][0] = __expf(s[j][0] + t0.x);
                s[j][1] = __expf(s[j][1] + t0.y);
                s[j][2] = __expf(s[j][2] + t1.x);
                s[j][3] = __expf(s[j][3] + t1.y);
                sum0 += s[j][0] + s[j][1];
                sum1 += s[j][2] + s[j][3];
            }
            // O += P @ V : A-fragments via intra-quad shuffle relayout
            #pragma unroll
            for (int ks = 0; ks < 7; ks++) {
                float le1 = __shfl_sync(0xffffffffu, s[ks][0], src1);
                float lo1 = __shfl_sync(0xffffffffu, s[ks][1], src1);
                float he1 = __shfl_sync(0xffffffffu, s[ks][2], src1);
                float ho1 = __shfl_sync(0xffffffffu, s[ks][3], src1);
                float le2 = __shfl_sync(0xffffffffu, s[ks][0], src2);
                float lo2 = __shfl_sync(0xffffffffu, s[ks][1], src2);
                float he2 = __shfl_sync(0xffffffffu, s[ks][2], src2);
                float ho2 = __shfl_sync(0xffffffffu, s[ks][3], src2);
                uint32_t ap[4];
                ap[0] = f2tf32(odd ? lo1 : le1);
                ap[1] = f2tf32(odd ? ho1 : he1);
                ap[2] = f2tf32(odd ? lo2 : le2);
                ap[3] = f2tf32(odd ? ho2 : he2);
                #pragma unroll
                for (int nf = 0; nf < 4; nf++) {
                    uint32_t b[2];
                    const uint32_t* vb = sVT + (nf * 8 + g) * SVT_STR + n0 + ks * 8 + tig;
                    b[0] = vb[0]; b[1] = vb[4];
                    mma_tf32(o[nf], ap, b);
                }
            }
        }

        sum0 += __shfl_xor_sync(0xffffffffu, sum0, 1);
        sum0 += __shfl_xor_sync(0xffffffffu, sum0, 2);
        sum1 += __shfl_xor_sync(0xffffffffu, sum1, 1);
        sum1 += __shfl_xor_sync(0xffffffffu, sum1, 2);
        float inv0 = 1.0f / sum0, inv1 = 1.0f / sum1;

        #pragma unroll
        for (int nf = 0; nf < 4; nf++) {
            int col = head * HD + nf * 8 + tig * 2;
            if (row0 < NTOK) {
                float2 v; v.x = o[nf][0] * inv0; v.y = o[nf][1] * inv0;
                *(float2*)(g_owin + ((size_t)(win * NTOK + row0)) * Cc + col) = v;
            }
            if (row0 + 8 < NTOK) {
                float2 v; v.x = o[nf][2] * inv1; v.y = o[nf][3] * inv1;
                *(float2*)(g_owin + ((size_t)(win * NTOK + row0 + 8)) * Cc + col) = v;
            }
        }
    }
}

// ---------------- launch ----------------
extern "C" void kernel_launch(void* const* d_in, const int* in_sizes, int n_in,
                              void* d_out, int out_size) {
    const float* x       = (const float*)d_in[0];
    const float* norm1_g = (const float*)d_in[1];
    const float* norm1_b = (const float*)d_in[2];
    const float* qkv_w   = (const float*)d_in[3];
    const float* qkv_b   = (const float*)d_in[4];
    const float* rel_b   = (const float*)d_in[5];
    const float* proj_w  = (const float*)d_in[6];
    const float* proj_b  = (const float*)d_in[7];
    const float* norm2_g = (const float*)d_in[8];
    const float* norm2_b = (const float*)d_in[9];
    const float* fc1_w   = (const float*)d_in[10];
    const float* fc1_b   = (const float*)d_in[11];
    const float* fc2_w   = (const float*)d_in[12];
    const float* fc2_b   = (const float*)d_in[13];
    float* out = (float*)d_out;

    float *hwin, *owin, *x1, *h2, *m1;
    cudaGetSymbolAddress((void**)&hwin, g_hwin);
    cudaGetSymbolAddress((void**)&owin, g_owin);
    cudaGetSymbolAddress((void**)&x1, g_x1);
    cudaGetSymbolAddress((void**)&h2, g_h2);
    cudaGetSymbolAddress((void**)&m1, g_m1);

    cudaFuncSetAttribute(attn_mma_kernel, cudaFuncAttributeMaxDynamicSharedMemorySize, SMEM_ATTN);

    tbl_kernel<<<(TBL_ENTRIES + 255) / 256, 256>>>(rel_b);
    ln_kernel<true><<<TOK / 4, 128>>>(x, norm1_g, norm1_b, hwin);
    gemm_tc<0><<<dim3(288 / 32, TOK / 128), 128>>>(hwin, qkv_w, qkv_b, nullptr, nullptr, 96, 288);
    attn_mma_kernel<<<BWIN * HEADS, 256, SMEM_ATTN>>>();
    gemm_tc<1><<<dim3(96 / 32, TOK / 128), 128>>>(owin, proj_w, proj_b, x, nullptr, 96, 96);
    ln_kernel<false><<<TOK / 4, 128>>>(x1, norm2_g, norm2_b, h2);
    gemm_tc<2><<<dim3(HIDDEN / 32, TOK / 128), 128>>>(h2, fc1_w, fc1_b, nullptr, m1, 96, HIDDEN);
    gemm_tc<3><<<dim3(96 / 32, TOK / 128), 128>>>(m1, fc2_w, fc2_b, nullptr, out, HIDDEN, 96);
}

// round 7
// speedup vs baseline: 3.7257x; 1.2430x over previous
#include <cuda_runtime.h>
#include <cstdint>

// ---------------- problem constants ----------------
#define Bx      2
#define Tt      16
#define Hh      56
#define Ww      56
#define Cc      96
#define HEADS   3
#define HD      32
#define WT      8
#define WH      7
#define WWIN    7
#define STs     4
#define SHs     3
#define SWs     3
#define NTOK    392
#define NWIN    128
#define BWIN    256
#define LL      50176
#define TOK     100352
#define HIDDEN  384
#define SCALE   0.1767766952966369f

#define TBL_ROWSTRIDE 392
#define TBL_CLS_STRIDE 156800   // 400*392
#define SMEM_GEMM ((128 * 100 + 96 * 100) * 4)   // 89600 B

// ---------------- scratch ----------------
__device__ float g_q[BWIN * HEADS * NTOK * HD + 256];
__device__ float g_k[BWIN * HEADS * NTOK * HD];
__device__ float g_v[BWIN * HEADS * NTOK * HD];
__device__ float g_owin[TOK * Cc];
__device__ float g_x1[TOK * Cc];
__device__ float g_m1[TOK * HIDDEN];
__device__ float g_tbl[24 * TBL_CLS_STRIDE];

__device__ __forceinline__ int orig_index(int wloc, int n) {
    int wt = wloc >> 6;
    int wh = (wloc >> 3) & 7;
    int ww = wloc & 7;
    int it = n / 49;
    int r  = n % 49;
    int ih = r / 7;
    int iw = r % 7;
    int t = wt * WT + it;
    int h = wh * WH + ih;
    int w = ww * WWIN + iw;
    int to = (t + STs) & 15;
    int ho = h + SHs; if (ho >= Hh) ho -= Hh;
    int wo = w + SWs; if (wo >= Ww) wo -= Ww;
    return (to * Hh + ho) * Ww + wo;
}

__device__ __forceinline__ void cp16(void* dst, const void* src) {
    uint32_t d = (uint32_t)__cvta_generic_to_shared(dst);
    asm volatile("cp.async.cg.shared.global [%0], [%1], 16;" :: "r"(d), "l"(src));
}
__device__ __forceinline__ void cp_commit_wait() {
    asm volatile("cp.async.commit_group;");
    asm volatile("cp.async.wait_group 0;");
}

// ---------------- bias+mask table: grid (q, cls3), 256 thr, k strided ----------------
__global__ __launch_bounds__(256) void tbl_kernel(const float* __restrict__ rel_bias) {
    int q = blockIdx.x;
    int cls3 = blockIdx.y;
    int head = cls3 % 3, cls = cls3 / 3;
    int it1 = q / 49, r1 = q % 49, ih1 = r1 / 7, iw1 = r1 % 7;
    int bt = (cls >> 2) & 1, bh = (cls >> 1) & 1, bw = cls & 1;
    int rt1 = bt ? (it1 < 4 ? 1 : 2) : 0;
    int rh1 = bh ? (ih1 < 4 ? 1 : 2) : 0;
    int rw1 = bw ? (iw1 < 4 ? 1 : 2) : 0;
    float* dst = g_tbl + (size_t)cls3 * TBL_CLS_STRIDE + q * TBL_ROWSTRIDE;
    for (int k = threadIdx.x; k < NTOK; k += 256) {
        int it2 = k / 49, r2 = k % 49, ih2 = r2 / 7, iw2 = r2 % 7;
        float b = rel_bias[((it1 - it2 + 7) * 15 + (ih1 - ih2 + 6) * 13 + (iw1 - iw2 + 6)) * 3 + head];
        int rt2 = bt ? (it2 < 4 ? 1 : 2) : 0;
        int rh2 = bh ? (ih2 < 4 ? 1 : 2) : 0;
        int rw2 = bw ? (iw2 < 4 ? 1 : 2) : 0;
        if (rt1 != rt2 || rh1 != rh2 || rw1 != rw2) b -= 100.0f;
        dst[k] = b;
    }
}

// ---------------- tf32 MMA ----------------
__device__ __forceinline__ void mma_tf32(float* c, const uint32_t* a, const uint32_t* b) {
    asm volatile(
        "mma.sync.aligned.m16n8k8.row.col.f32.tf32.tf32.f32 "
        "{%0,%1,%2,%3},{%4,%5,%6,%7},{%8,%9},{%0,%1,%2,%3};"
        : "+f"(c[0]), "+f"(c[1]), "+f"(c[2]), "+f"(c[3])
        : "r"(a[0]), "r"(a[1]), "r"(a[2]), "r"(a[3]), "r"(b[0]), "r"(b[1]));
}
#define FB(x) __float_as_uint(x)

// ---------------- unified GEMM: tile 128x96, optional fused LN on A rows ----------------
// EPI 0: qkv split+scale (A = x, gathered, LN)     EPI 1: proj + scatter + residual
// EPI 2: fc1 + gelu (A = g_x1, LN)                 EPI 3: fc2 + residual -> Cout
template<int EPI, bool LN, bool GATHER, int KTOT>
__global__ __launch_bounds__(256, 2) void gemm_tc(const float* __restrict__ A,
                                                  const float* __restrict__ Bw,
                                                  const float* __restrict__ bias,
                                                  const float* __restrict__ gam,
                                                  const float* __restrict__ bet,
                                                  const float* __restrict__ res,
                                                  float* __restrict__ Cout) {
    extern __shared__ float dsm[];
    float (*sA)[100] = (float(*)[100])dsm;
    float (*sB)[100] = (float(*)[100])(dsm + 128 * 100);

    int m0 = blockIdx.y * 128;
    int n0 = blockIdx.x * 96;
    int tid = threadIdx.x;
    int lane = tid & 31, warp = tid >> 5;
    int wm = warp >> 1, wn = warp & 1;
    int g = lane >> 2, tig = lane & 3;

    float acc[2][6][4];
    #pragma unroll
    for (int i = 0; i < 2; i++)
        #pragma unroll
        for (int j = 0; j < 6; j++)
            #pragma unroll
            for (int c = 0; c < 4; c++) acc[i][j][c] = 0.0f;

    #pragma unroll 1
    for (int ch = 0; ch < KTOT / 96; ch++) {
        // A tile: 128 rows x 96 cols (24 x 16B segs per row)
        for (int s = tid; s < 128 * 24; s += 256) {
            int row = s / 24, c4 = (s % 24) * 4;
            const float* src;
            if (GATHER) {
                int m = m0 + row;
                int w = m / NTOK, n = m % NTOK;
                int b = w >> 7;
                src = A + ((size_t)b * LL + orig_index(w & 127, n)) * Cc + c4;
            } else {
                src = A + (size_t)(m0 + row) * KTOT + ch * 96 + c4;
            }
            cp16(&sA[row][c4], src);
        }
        // B tile: 96 rows x 96 cols
        for (int s = tid; s < 96 * 24; s += 256) {
            int row = s / 24, c4 = (s % 24) * 4;
            cp16(&sB[row][c4], Bw + (size_t)(n0 + row) * KTOT + ch * 96 + c4);
        }
        cp_commit_wait();
        __syncthreads();

        if (LN) {   // K=96 only: full rows resident -> LayerNorm in place
            int r = tid >> 1, hf = tid & 1;
            float* rowp = sA[r] + hf * 48;
            float s1 = 0.0f, s2 = 0.0f;
            #pragma unroll
            for (int i = 0; i < 48; i++) { float v = rowp[i]; s1 += v; s2 += v * v; }
            s1 += __shfl_xor_sync(0xffffffffu, s1, 1);
            s2 += __shfl_xor_sync(0xffffffffu, s2, 1);
            float mean = s1 * (1.0f / 96.0f);
            float var = s2 * (1.0f / 96.0f) - mean * mean;
            float rstd = rsqrtf(var + 1e-5f);
            #pragma unroll
            for (int i = 0; i < 48; i++) {
                int c = hf * 48 + i;
                rowp[i] = (rowp[i] - mean) * rstd * __ldg(gam + c) + __ldg(bet + c);
            }
            __syncthreads();
        }

        #pragma unroll
        for (int kb = 0; kb < 96; kb += 8) {
            uint32_t a[2][4], b[6][2];
            #pragma unroll
            for (int i = 0; i < 2; i++) {
                int r = wm * 32 + i * 16 + g;
                a[i][0] = FB(sA[r][kb + tig]);
                a[i][1] = FB(sA[r + 8][kb + tig]);
                a[i][2] = FB(sA[r][kb + tig + 4]);
                a[i][3] = FB(sA[r + 8][kb + tig + 4]);
            }
            #pragma unroll
            for (int j = 0; j < 6; j++) {
                int n = wn * 48 + j * 8 + g;
                b[j][0] = FB(sB[n][kb + tig]);
                b[j][1] = FB(sB[n][kb + tig + 4]);
            }
            #pragma unroll
            for (int i = 0; i < 2; i++)
                #pragma unroll
                for (int j = 0; j < 6; j++) mma_tf32(acc[i][j], a[i], b[j]);
        }
        __syncthreads();
    }

    #pragma unroll
    for (int i = 0; i < 2; i++)
        #pragma unroll
        for (int j = 0; j < 6; j++)
            #pragma unroll
            for (int c = 0; c < 4; c++) {
                int m = m0 + wm * 32 + i * 16 + g + ((c >> 1) << 3);
                int col = n0 + wn * 48 + j * 8 + tig * 2 + (c & 1);
                float val = acc[i][j][c] + bias[col];
                if (EPI == 0) {
                    int w = m / NTOK, n = m % NTOK;
                    int part = col / 96;
                    int hh = col % 96;
                    int head = hh >> 5, d = hh & 31;
                    size_t dst = (((size_t)(w * 3 + head)) * NTOK + n) * HD + d;
                    if (part == 0)      g_q[dst] = val * SCALE;
                    else if (part == 1) g_k[dst] = val;
                    else                g_v[dst] = val;
                } else if (EPI == 1) {
                    int w = m / NTOK, n = m % NTOK;
                    int b2 = w >> 7, wloc = w & 127;
                    int l = orig_index(wloc, n);
                    size_t dst = ((size_t)b2 * LL + l) * Cc + col;
                    g_x1[dst] = res[dst] + val;
                } else if (EPI == 2) {
                    float gval = 0.5f * val * (1.0f + erff(val * 0.70710678118654752f));
                    Cout[(size_t)m * HIDDEN + col] = gval;
                } else {
                    size_t dst = (size_t)m * Cc + col;
                    Cout[dst] = g_x1[dst] + val;
                }
            }
}

// ---------------- MMA attention (shuffle-P, 2 blocks/SM) ----------------
#define SK_STR   36
#define SVT_STR  404
#define SK_OFF   0
#define SVT_OFF  (392 * SK_STR)
#define SMEM_ATTN ((SVT_OFF + 32 * SVT_STR) * 4)    // 108,160 B

__global__ __launch_bounds__(256, 2) void attn_mma_kernel() {
    extern __shared__ uint32_t smem[];
    uint32_t* sK  = smem + SK_OFF;
    uint32_t* sVT = smem + SVT_OFF;

    int win  = blockIdx.x / HEADS;
    int head = blockIdx.x % HEADS;
    int tid  = threadIdx.x;
    int lane = tid & 31, warp = tid >> 5;
    int g = lane >> 2, tig = lane & 3;

    const float* Kg = g_k + ((size_t)(win * HEADS + head)) * NTOK * HD;
    const float* Vg = g_v + ((size_t)(win * HEADS + head)) * NTOK * HD;
    const float* Qg = g_q + ((size_t)(win * HEADS + head)) * NTOK * HD;

    int wloc = win & 127;
    int wt = wloc >> 6, wh = (wloc >> 3) & 7, ww = wloc & 7;
    int cls = ((wt == 1) << 2) | ((wh == 7) << 1) | (ww == 7);
    const float* tbl = g_tbl + (size_t)(cls * 3 + head) * TBL_CLS_STRIDE;

    for (int i = tid; i < NTOK * 8; i += 256) {
        float4 kv = ((const float4*)Kg)[i];
        int row = i >> 3, c = (i & 7) << 2;
        uint32_t* d = sK + row * SK_STR + c;
        d[0] = FB(kv.x); d[1] = FB(kv.y); d[2] = FB(kv.z); d[3] = FB(kv.w);
        float4 vv = ((const float4*)Vg)[i];
        sVT[(c + 0) * SVT_STR + row] = FB(vv.x);
        sVT[(c + 1) * SVT_STR + row] = FB(vv.y);
        sVT[(c + 2) * SVT_STR + row] = FB(vv.z);
        sVT[(c + 3) * SVT_STR + row] = FB(vv.w);
    }
    __syncthreads();

    int src1 = g * 4 + (tig >> 1);
    int src2 = src1 + 2;
    bool odd = (tig & 1);

    for (int mt = warp; mt < 25; mt += 8) {
        int row0 = mt * 16 + g;
        uint32_t aq[4][4];
        const float* Qr = Qg + row0 * HD;
        #pragma unroll
        for (int ks = 0; ks < 4; ks++) {
            aq[ks][0] = FB(__ldg(Qr + ks * 8 + tig));
            aq[ks][1] = FB(__ldg(Qr + 256 + ks * 8 + tig));
            aq[ks][2] = FB(__ldg(Qr + ks * 8 + tig + 4));
            aq[ks][3] = FB(__ldg(Qr + 256 + ks * 8 + tig + 4));
        }

        float o[4][4];
        #pragma unroll
        for (int nf = 0; nf < 4; nf++)
            #pragma unroll
            for (int e = 0; e < 4; e++) o[nf][e] = 0.0f;
        float sum0 = 0.0f, sum1 = 0.0f;

        for (int c = 0; c < 7; c++) {
            int n0 = c * 56;
            float s[7][4];
            #pragma unroll
            for (int j = 0; j < 7; j++)
                #pragma unroll
                for (int e = 0; e < 4; e++) s[j][e] = 0.0f;
            #pragma unroll
            for (int ks = 0; ks < 4; ks++) {
                #pragma unroll
                for (int j = 0; j < 7; j++) {
                    uint32_t b[2];
                    const uint32_t* kb = sK + (n0 + j * 8 + g) * SK_STR + ks * 8 + tig;
                    b[0] = kb[0]; b[1] = kb[4];
                    mma_tf32(s[j], aq[ks], b);
                }
            }
            #pragma unroll
            for (int j = 0; j < 7; j++) {
                int colBase = n0 + j * 8 + tig * 2;
                float2 t0 = *(const float2*)(tbl + (size_t)row0 * TBL_ROWSTRIDE + colBase);
                float2 t1 = *(const float2*)(tbl + (size_t)(row0 + 8) * TBL_ROWSTRIDE + colBase);
                s[j][0] = __expf(s[j][0] + t0.x);
                s[j][1] = __expf(s[j][1] + t0.y);
                s[j][2] = __expf(s[j][2] + t1.x);
                s[j][3] = __expf(s[j][3] + t1.y);
                sum0 += s[j][0] + s[j][1];
                sum1 += s[j][2] + s[j][3];
            }
            #pragma unroll
            for (int ks = 0; ks < 7; ks++) {
                float le1 = __shfl_sync(0xffffffffu, s[ks][0], src1);
                float lo1 = __shfl_sync(0xffffffffu, s[ks][1], src1);
                float he1 = __shfl_sync(0xffffffffu, s[ks][2], src1);
                float ho1 = __shfl_sync(0xffffffffu, s[ks][3], src1);
                float le2 = __shfl_sync(0xffffffffu, s[ks][0], src2);
                float lo2 = __shfl_sync(0xffffffffu, s[ks][1], src2);
                float he2 = __shfl_sync(0xffffffffu, s[ks][2], src2);
                float ho2 = __shfl_sync(0xffffffffu, s[ks][3], src2);
                uint32_t ap[4];
                ap[0] = FB(odd ? lo1 : le1);
                ap[1] = FB(odd ? ho1 : he1);
                ap[2] = FB(odd ? lo2 : le2);
                ap[3] = FB(odd ? ho2 : he2);
                #pragma unroll
                for (int nf = 0; nf < 4; nf++) {
                    uint32_t b[2];
                    const uint32_t* vb = sVT + (nf * 8 + g) * SVT_STR + n0 + ks * 8 + tig;
                    b[0] = vb[0]; b[1] = vb[4];
                    mma_tf32(o[nf], ap, b);
                }
            }
        }

        sum0 += __shfl_xor_sync(0xffffffffu, sum0, 1);
        sum0 += __shfl_xor_sync(0xffffffffu, sum0, 2);
        sum1 += __shfl_xor_sync(0xffffffffu, sum1, 1);
        sum1 += __shfl_xor_sync(0xffffffffu, sum1, 2);
        float inv0 = 1.0f / sum0, inv1 = 1.0f / sum1;

        #pragma unroll
        for (int nf = 0; nf < 4; nf++) {
            int col = head * HD + nf * 8 + tig * 2;
            if (row0 < NTOK) {
                float2 v; v.x = o[nf][0] * inv0; v.y = o[nf][1] * inv0;
                *(float2*)(g_owin + ((size_t)(win * NTOK + row0)) * Cc + col) = v;
            }
            if (row0 + 8 < NTOK) {
                float2 v; v.x = o[nf][2] * inv1; v.y = o[nf][3] * inv1;
                *(float2*)(g_owin + ((size_t)(win * NTOK + row0 + 8)) * Cc + col) = v;
            }
        }
    }
}

// ---------------- launch ----------------
extern "C" void kernel_launch(void* const* d_in, const int* in_sizes, int n_in,
                              void* d_out, int out_size) {
    const float* x       = (const float*)d_in[0];
    const float* norm1_g = (const float*)d_in[1];
    const float* norm1_b = (const float*)d_in[2];
    const float* qkv_w   = (const float*)d_in[3];
    const float* qkv_b   = (const float*)d_in[4];
    const float* rel_b   = (const float*)d_in[5];
    const float* proj_w  = (const float*)d_in[6];
    const float* proj_b  = (const float*)d_in[7];
    const float* norm2_g = (const float*)d_in[8];
    const float* norm2_b = (const float*)d_in[9];
    const float* fc1_w   = (const float*)d_in[10];
    const float* fc1_b   = (const float*)d_in[11];
    const float* fc2_w   = (const float*)d_in[12];
    const float* fc2_b   = (const float*)d_in[13];
    float* out = (float*)d_out;

    float *owin, *x1, *m1;
    cudaGetSymbolAddress((void**)&owin, g_owin);
    cudaGetSymbolAddress((void**)&x1, g_x1);
    cudaGetSymbolAddress((void**)&m1, g_m1);

    cudaFuncSetAttribute(attn_mma_kernel, cudaFuncAttributeMaxDynamicSharedMemorySize, SMEM_ATTN);
    cudaFuncSetAttribute(gemm_tc<0, true,  true,  96>,  cudaFuncAttributeMaxDynamicSharedMemorySize, SMEM_GEMM);
    cudaFuncSetAttribute(gemm_tc<1, false, false, 96>,  cudaFuncAttributeMaxDynamicSharedMemorySize, SMEM_GEMM);
    cudaFuncSetAttribute(gemm_tc<2, true,  false, 96>,  cudaFuncAttributeMaxDynamicSharedMemorySize, SMEM_GEMM);
    cudaFuncSetAttribute(gemm_tc<3, false, false, 384>, cudaFuncAttributeMaxDynamicSharedMemorySize, SMEM_GEMM);

    // 0. bias+mask table
    tbl_kernel<<<dim3(392, 24), 256>>>(rel_b);
    // 1. QKV gemm (fused LN1 + roll/partition gather)
    gemm_tc<0, true, true, 96><<<dim3(3, TOK / 128), 256, SMEM_GEMM>>>(
        x, qkv_w, qkv_b, norm1_g, norm1_b, nullptr, nullptr);
    // 2. attention
    attn_mma_kernel<<<BWIN * HEADS, 256, SMEM_ATTN>>>();
    // 3. proj + window reverse + residual -> g_x1
    gemm_tc<1, false, false, 96><<<dim3(1, TOK / 128), 256, SMEM_GEMM>>>(
        owin, proj_w, proj_b, nullptr, nullptr, x, nullptr);
    // 4. fc1 (fused LN2) + gelu -> g_m1
    gemm_tc<2, true, false, 96><<<dim3(4, TOK / 128), 256, SMEM_GEMM>>>(
        x1, fc1_w, fc1_b, norm2_g, norm2_b, nullptr, m1);
    // 5. fc2 + residual -> out
    gemm_tc<3, false, false, 384><<<dim3(1, TOK / 128), 256, SMEM_GEMM>>>(
        m1, fc2_w, fc2_b, nullptr, nullptr, nullptr, out);
}

// round 11
// speedup vs baseline: 5.4481x; 1.4623x over previous
#include <cuda_runtime.h>
#include <cuda_fp16.h>
#include <cstdint>

// ---------------- problem constants ----------------
#define Bx      2
#define Tt      16
#define Hh      56
#define Ww      56
#define Cc      96
#define HEADS   3
#define HD      32
#define WT      8
#define WH      7
#define WWIN    7
#define STs     4
#define SHs     3
#define SWs     3
#define NTOK    392
#define NWIN    128
#define BWIN    256
#define LL      50176
#define TOK     100352
#define HIDDEN  384
#define SCALE   0.1767766952966369f

#define TBL_ROWSTRIDE 392
#define TBL_CLS_STRIDE 156800   // 400*392
#define AST 104                 // fp16 smem tile stride
#define SMEM_GEMM ((128 * AST + 96 * AST) * 2)   // 46592 B

// ---------------- scratch ----------------
__device__ __half g_q[BWIN * HEADS * NTOK * HD + 256];
__device__ __half g_k[BWIN * HEADS * NTOK * HD];
__device__ __half g_v[BWIN * HEADS * NTOK * HD];
__device__ __half g_owin[TOK * Cc];
__device__ float  g_x1[TOK * Cc];
__device__ __half g_m1[TOK * HIDDEN];
__device__ float  g_tbl[24 * TBL_CLS_STRIDE];

__device__ __forceinline__ int orig_index(int wloc, int n) {
    int wt = wloc >> 6;
    int wh = (wloc >> 3) & 7;
    int ww = wloc & 7;
    int it = n / 49;
    int r  = n % 49;
    int ih = r / 7;
    int iw = r % 7;
    int t = wt * WT + it;
    int h = wh * WH + ih;
    int w = ww * WWIN + iw;
    int to = (t + STs) & 15;
    int ho = h + SHs; if (ho >= Hh) ho -= Hh;
    int wo = w + SWs; if (wo >= Ww) wo -= Ww;
    return (to * Hh + ho) * Ww + wo;
}

__device__ __forceinline__ void cp16(void* dst, const void* src) {
    uint32_t d = (uint32_t)__cvta_generic_to_shared(dst);
    asm volatile("cp.async.cg.shared.global [%0], [%1], 16;" :: "r"(d), "l"(src));
}
__device__ __forceinline__ void cp_commit_wait() {
    asm volatile("cp.async.commit_group;");
    asm volatile("cp.async.wait_group 0;");
}
__device__ __forceinline__ uint32_t pack_h2(float lo, float hi) {
    __half2 h = __floats2half2_rn(lo, hi);
    return *(uint32_t*)&h;
}
__device__ __forceinline__ void mma_f16(float* c, const uint32_t* a, const uint32_t* b) {
    asm volatile(
        "mma.sync.aligned.m16n8k16.row.col.f32.f16.f16.f32 "
        "{%0,%1,%2,%3},{%4,%5,%6,%7},{%8,%9},{%0,%1,%2,%3};"
        : "+f"(c[0]), "+f"(c[1]), "+f"(c[2]), "+f"(c[3])
        : "r"(a[0]), "r"(a[1]), "r"(a[2]), "r"(a[3]), "r"(b[0]), "r"(b[1]));
}
__device__ __forceinline__ void mma_f16_k8(float* c, const uint32_t* a, uint32_t b) {
    asm volatile(
        "mma.sync.aligned.m16n8k8.row.col.f32.f16.f16.f32 "
        "{%0,%1,%2,%3},{%4,%5},{%6},{%0,%1,%2,%3};"
        : "+f"(c[0]), "+f"(c[1]), "+f"(c[2]), "+f"(c[3])
        : "r"(a[0]), "r"(a[1]), "r"(b));
}

// ---------------- bias+mask table ----------------
__global__ __launch_bounds__(256) void tbl_kernel(const float* __restrict__ rel_bias) {
    int q = blockIdx.x;
    int cls3 = blockIdx.y;
    int head = cls3 % 3, cls = cls3 / 3;
    int it1 = q / 49, r1 = q % 49, ih1 = r1 / 7, iw1 = r1 % 7;
    int bt = (cls >> 2) & 1, bh = (cls >> 1) & 1, bw = cls & 1;
    int rt1 = bt ? (it1 < 4 ? 1 : 2) : 0;
    int rh1 = bh ? (ih1 < 4 ? 1 : 2) : 0;
    int rw1 = bw ? (iw1 < 4 ? 1 : 2) : 0;
    float* dst = g_tbl + (size_t)cls3 * TBL_CLS_STRIDE + q * TBL_ROWSTRIDE;
    for (int k = threadIdx.x; k < NTOK; k += 256) {
        int it2 = k / 49, r2 = k % 49, ih2 = r2 / 7, iw2 = r2 % 7;
        float b = rel_bias[((it1 - it2 + 7) * 15 + (ih1 - ih2 + 6) * 13 + (iw1 - iw2 + 6)) * 3 + head];
        int rt2 = bt ? (it2 < 4 ? 1 : 2) : 0;
        int rh2 = bh ? (ih2 < 4 ? 1 : 2) : 0;
        int rw2 = bw ? (iw2 < 4 ? 1 : 2) : 0;
        if (rt1 != rt2 || rh1 != rh2 || rw1 != rw2) b -= 100.0f;
        dst[k] = b;
    }
}

// ---------------- unified fp16 GEMM: tile 128x96 ----------------
// EPI 0: qkv split+scale (A=x fp32, gather, LN)  EPI 1: proj(A=g_owin fp16) + scatter + residual
// EPI 2: fc1 (A=g_x1 fp32, LN) + gelu            EPI 3: fc2 (A=g_m1 fp16) + residual -> Cout
template<int EPI, bool LN, bool GATHER, int KTOT>
__global__ __launch_bounds__(256, 2) void gemm_tc(const void* __restrict__ Ain,
                                                  const float* __restrict__ Bw,
                                                  const float* __restrict__ bias,
                                                  const float* __restrict__ gam,
                                                  const float* __restrict__ bet,
                                                  const float* __restrict__ res,
                                                  float* __restrict__ Cout) {
    extern __shared__ __half sm[];
    __half (*sA)[AST] = (__half(*)[AST])sm;
    __half (*sB)[AST] = (__half(*)[AST])(sm + 128 * AST);

    int m0 = blockIdx.y * 128;
    int n0 = blockIdx.x * 96;
    int tid = threadIdx.x;
    int lane = tid & 31, warp = tid >> 5;
    int wm = warp >> 1, wn = warp & 1;
    int g = lane >> 2, tig = lane & 3;

    float acc[2][6][4];
    #pragma unroll
    for (int i = 0; i < 2; i++)
        #pragma unroll
        for (int j = 0; j < 6; j++)
            #pragma unroll
            for (int c = 0; c < 4; c++) acc[i][j][c] = 0.0f;

    #pragma unroll 1
    for (int ch = 0; ch < KTOT / 96; ch++) {
        if (!LN) {  // A already fp16 in gmem: async copy (12 x 16B segs per row)
            const __half* Ah = (const __half*)Ain;
            for (int s = tid; s < 128 * 12; s += 256) {
                int row = s / 12, seg = s % 12;
                cp16(&sA[row][seg * 8], Ah + (size_t)(m0 + row) * KTOT + ch * 96 + seg * 8);
            }
        }
        // B tile (weights fp32 -> fp16)
        for (int s = tid; s < 96 * 24; s += 256) {
            int row = s / 24, f4 = s % 24;
            float4 v = __ldg((const float4*)(Bw + (size_t)(n0 + row) * KTOT + ch * 96) + f4);
            uint32_t* d = (uint32_t*)&sB[row][f4 * 4];
            d[0] = pack_h2(v.x, v.y);
            d[1] = pack_h2(v.z, v.w);
        }
        if (LN) {   // fp32 A rows -> registers -> LN -> fp16 smem (4 threads/row)
            int q4 = tid & 3, rr = tid >> 2;
            #pragma unroll
            for (int p = 0; p < 2; p++) {
                int row = p * 64 + rr;
                const float* src;
                if (GATHER) {
                    int m = m0 + row;
                    int w = m / NTOK, n = m % NTOK;
                    int b = w >> 7;
                    src = (const float*)Ain + ((size_t)b * LL + orig_index(w & 127, n)) * Cc + q4 * 24;
                } else {
                    src = (const float*)Ain + (size_t)(m0 + row) * 96 + q4 * 24;
                }
                float v[24];
                #pragma unroll
                for (int i = 0; i < 6; i++) *(float4*)&v[i * 4] = __ldg((const float4*)src + i);
                float s1 = 0.0f, s2 = 0.0f;
                #pragma unroll
                for (int i = 0; i < 24; i++) { s1 += v[i]; s2 += v[i] * v[i]; }
                s1 += __shfl_xor_sync(0xffffffffu, s1, 1);
                s1 += __shfl_xor_sync(0xffffffffu, s1, 2);
                s2 += __shfl_xor_sync(0xffffffffu, s2, 1);
                s2 += __shfl_xor_sync(0xffffffffu, s2, 2);
                float mean = s1 * (1.0f / 96.0f);
                float rstd = rsqrtf(s2 * (1.0f / 96.0f) - mean * mean + 1e-5f);
                #pragma unroll
                for (int i = 0; i < 12; i++) {
                    int c = q4 * 24 + 2 * i;
                    float a0 = (v[2 * i] - mean) * rstd * __ldg(gam + c) + __ldg(bet + c);
                    float a1 = (v[2 * i + 1] - mean) * rstd * __ldg(gam + c + 1) + __ldg(bet + c + 1);
                    *(uint32_t*)&sA[row][c] = pack_h2(a0, a1);
                }
            }
        } else {
            cp_commit_wait();
        }
        __syncthreads();

        #pragma unroll
        for (int ks = 0; ks < 6; ks++) {
            int kb = ks * 16;
            uint32_t a[2][4], b[6][2];
            #pragma unroll
            for (int i = 0; i < 2; i++) {
                int r = wm * 32 + i * 16 + g;
                a[i][0] = *(const uint32_t*)&sA[r][kb + 2 * tig];
                a[i][1] = *(const uint32_t*)&sA[r + 8][kb + 2 * tig];
                a[i][2] = *(const uint32_t*)&sA[r][kb + 2 * tig + 8];
                a[i][3] = *(const uint32_t*)&sA[r + 8][kb + 2 * tig + 8];
            }
            #pragma unroll
            for (int j = 0; j < 6; j++) {
                int n = wn * 48 + j * 8 + g;
                b[j][0] = *(const uint32_t*)&sB[n][kb + 2 * tig];
                b[j][1] = *(const uint32_t*)&sB[n][kb + 2 * tig + 8];
            }
            #pragma unroll
            for (int i = 0; i < 2; i++)
                #pragma unroll
                for (int j = 0; j < 6; j++) mma_f16(acc[i][j], a[i], b[j]);
        }
        __syncthreads();
    }

    #pragma unroll
    for (int i = 0; i < 2; i++)
        #pragma unroll
        for (int j = 0; j < 6; j++)
            #pragma unroll
            for (int p = 0; p < 2; p++) {
                int m = m0 + wm * 32 + i * 16 + g + p * 8;
                int col = n0 + wn * 48 + j * 8 + tig * 2;
                float v0 = acc[i][j][2 * p] + bias[col];
                float v1 = acc[i][j][2 * p + 1] + bias[col + 1];
                if (EPI == 0) {
                    int w = m / NTOK, n = m % NTOK;
                    int part = col / 96;
                    int hh = col % 96;
                    int head = hh >> 5, d = hh & 31;
                    size_t dst = (((size_t)(w * 3 + head)) * NTOK + n) * HD + d;
                    if (part == 0)
                        *(__half2*)(g_q + dst) = __floats2half2_rn(v0 * SCALE, v1 * SCALE);
                    else if (part == 1)
                        *(__half2*)(g_k + dst) = __floats2half2_rn(v0, v1);
                    else
                        *(__half2*)(g_v + dst) = __floats2half2_rn(v0, v1);
                } else if (EPI == 1) {
                    int w = m / NTOK, n = m % NTOK;
                    int b2 = w >> 7, wloc = w & 127;
                    size_t dst = ((size_t)b2 * LL + orig_index(wloc, n)) * Cc + col;
                    float2 r2 = *(const float2*)(res + dst);
                    float2 o2; o2.x = r2.x + v0; o2.y = r2.y + v1;
                    *(float2*)(g_x1 + dst) = o2;
                } else if (EPI == 2) {
                    float g0 = 0.5f * v0 * (1.0f + erff(v0 * 0.70710678118654752f));
                    float g1 = 0.5f * v1 * (1.0f + erff(v1 * 0.70710678118654752f));
                    *(__half2*)(g_m1 + (size_t)m * HIDDEN + col) = __floats2half2_rn(g0, g1);
                } else {
                    size_t dst = (size_t)m * Cc + col;
                    float2 x2 = *(const float2*)(g_x1 + dst);
                    float2 o2; o2.x = x2.x + v0; o2.y = x2.y + v1;
                    *(float2*)(Cout + dst) = o2;
                }
            }
}

// ---------------- fp16 MMA attention ----------------
#define SK_STR   40
#define SVT_STR  408
#define SMEM_ATTN ((392 * SK_STR + 32 * SVT_STR) * 2)   // 57472 B

__global__ __launch_bounds__(256, 2) void attn_mma_kernel() {
    extern __shared__ __half sm[];
    __half (*sK)[SK_STR] = (__half(*)[SK_STR])sm;
    __half* sVT = sm + 392 * SK_STR;

    int win  = blockIdx.x / HEADS;
    int head = blockIdx.x % HEADS;
    int tid  = threadIdx.x;
    int lane = tid & 31, warp = tid >> 5;
    int g = lane >> 2, tig = lane & 3;

    const __half* Kg = g_k + ((size_t)(win * HEADS + head)) * NTOK * HD;
    const __half* Vg = g_v + ((size_t)(win * HEADS + head)) * NTOK * HD;
    const __half* Qg = g_q + ((size_t)(win * HEADS + head)) * NTOK * HD;

    int wloc = win & 127;
    int wt = wloc >> 6, wh = (wloc >> 3) & 7, ww = wloc & 7;
    int cls = ((wt == 1) << 2) | ((wh == 7) << 1) | (ww == 7);
    const float* tbl = g_tbl + (size_t)(cls * 3 + head) * TBL_CLS_STRIDE;

    // K row-major, V transposed (both fp16, no conversion on K)
    for (int i = tid; i < NTOK * 4; i += 256) {
        int row = i >> 2, seg = i & 3;
        uint4 kv = *(const uint4*)(Kg + row * HD + seg * 8);
        *(uint4*)&sK[row][seg * 8] = kv;
        uint4 vv = *(const uint4*)(Vg + row * HD + seg * 8);
        const __half2* pp = (const __half2*)&vv;
        int c = seg * 8;
        #pragma unroll
        for (int e = 0; e < 4; e++) {
            sVT[(c + 2 * e) * SVT_STR + row]     = __low2half(pp[e]);
            sVT[(c + 2 * e + 1) * SVT_STR + row] = __high2half(pp[e]);
        }
    }
    __syncthreads();

    for (int mt = warp; mt < 25; mt += 8) {
        int row0 = mt * 16 + g;
        const __half* Qr = Qg + row0 * HD;
        uint32_t aq[2][4];
        #pragma unroll
        for (int ks = 0; ks < 2; ks++) {
            aq[ks][0] = *(const uint32_t*)(Qr + ks * 16 + 2 * tig);
            aq[ks][1] = *(const uint32_t*)(Qr + 256 + ks * 16 + 2 * tig);
            aq[ks][2] = *(const uint32_t*)(Qr + ks * 16 + 2 * tig + 8);
            aq[ks][3] = *(const uint32_t*)(Qr + 256 + ks * 16 + 2 * tig + 8);
        }

        float o[4][4];
        #pragma unroll
        for (int nf = 0; nf < 4; nf++)
            #pragma unroll
            for (int e = 0; e < 4; e++) o[nf][e] = 0.0f;
        float sum0 = 0.0f, sum1 = 0.0f;

        for (int c = 0; c < 7; c++) {
            int n0 = c * 56;
            float s[7][4];
            #pragma unroll
            for (int j = 0; j < 7; j++)
                #pragma unroll
                for (int e = 0; e < 4; e++) s[j][e] = 0.0f;
            #pragma unroll
            for (int ks = 0; ks < 2; ks++) {
                #pragma unroll
                for (int j = 0; j < 7; j++) {
                    const __half* kb = &sK[n0 + j * 8 + g][ks * 16 + 2 * tig];
                    uint32_t b[2];
                    b[0] = *(const uint32_t*)kb;
                    b[1] = *(const uint32_t*)(kb + 8);
                    mma_f16(s[j], aq[ks], b);
                }
            }
            // softmax numerators (logits bounded; mask -100 underflows to 0)
            #pragma unroll
            for (int j = 0; j < 7; j++) {
                int colBase = n0 + j * 8 + tig * 2;
                float2 t0 = *(const float2*)(tbl + (size_t)row0 * TBL_ROWSTRIDE + colBase);
                float2 t1 = *(const float2*)(tbl + (size_t)(row0 + 8) * TBL_ROWSTRIDE + colBase);
                s[j][0] = __expf(s[j][0] + t0.x);
                s[j][1] = __expf(s[j][1] + t0.y);
                s[j][2] = __expf(s[j][2] + t1.x);
                s[j][3] = __expf(s[j][3] + t1.y);
                sum0 += s[j][0] + s[j][1];
                sum1 += s[j][2] + s[j][3];
            }
            // O += P @ V : C-frags map directly onto fp16 A-frags (no shuffles)
            #pragma unroll
            for (int u = 0; u < 3; u++) {
                uint32_t ap[4];
                ap[0] = pack_h2(s[2 * u][0], s[2 * u][1]);
                ap[1] = pack_h2(s[2 * u][2], s[2 * u][3]);
                ap[2] = pack_h2(s[2 * u + 1][0], s[2 * u + 1][1]);
                ap[3] = pack_h2(s[2 * u + 1][2], s[2 * u + 1][3]);
                #pragma unroll
                for (int nf = 0; nf < 4; nf++) {
                    const __half* vb = sVT + (nf * 8 + g) * SVT_STR + n0 + u * 16 + 2 * tig;
                    uint32_t b[2];
                    b[0] = *(const uint32_t*)vb;
                    b[1] = *(const uint32_t*)(vb + 8);
                    mma_f16(o[nf], ap, b);
                }
            }
            {   // tail 8 keys (k8)
                uint32_t ap2[2];
                ap2[0] = pack_h2(s[6][0], s[6][1]);
                ap2[1] = pack_h2(s[6][2], s[6][3]);
                #pragma unroll
                for (int nf = 0; nf < 4; nf++) {
                    uint32_t b0 = *(const uint32_t*)(sVT + (nf * 8 + g) * SVT_STR + n0 + 48 + 2 * tig);
                    mma_f16_k8(o[nf], ap2, b0);
                }
            }
        }

        sum0 += __shfl_xor_sync(0xffffffffu, sum0, 1);
        sum0 += __shfl_xor_sync(0xffffffffu, sum0, 2);
        sum1 += __shfl_xor_sync(0xffffffffu, sum1, 1);
        sum1 += __shfl_xor_sync(0xffffffffu, sum1, 2);
        float inv0 = 1.0f / sum0, inv1 = 1.0f / sum1;

        #pragma unroll
        for (int nf = 0; nf < 4; nf++) {
            int col = head * HD + nf * 8 + tig * 2;
            *(__half2*)(g_owin + ((size_t)(win * NTOK + row0)) * Cc + col) =
                __floats2half2_rn(o[nf][0] * inv0, o[nf][1] * inv0);
            if (row0 + 8 < NTOK)
                *(__half2*)(g_owin + ((size_t)(win * NTOK + row0 + 8)) * Cc + col) =
                    __floats2half2_rn(o[nf][2] * inv1, o[nf][3] * inv1);
        }
    }
}

// ---------------- launch ----------------
extern "C" void kernel_launch(void* const* d_in, const int* in_sizes, int n_in,
                              void* d_out, int out_size) {
    const float* x       = (const float*)d_in[0];
    const float* norm1_g = (const float*)d_in[1];
    const float* norm1_b = (const float*)d_in[2];
    const float* qkv_w   = (const float*)d_in[3];
    const float* qkv_b   = (const float*)d_in[4];
    const float* rel_b   = (const float*)d_in[5];
    const float* proj_w  = (const float*)d_in[6];
    const float* proj_b  = (const float*)d_in[7];
    const float* norm2_g = (const float*)d_in[8];
    const float* norm2_b = (const float*)d_in[9];
    const float* fc1_w   = (const float*)d_in[10];
    const float* fc1_b   = (const float*)d_in[11];
    const float* fc2_w   = (const float*)d_in[12];
    const float* fc2_b   = (const float*)d_in[13];
    float* out = (float*)d_out;

    void *owin, *x1, *m1;
    cudaGetSymbolAddress(&owin, g_owin);
    cudaGetSymbolAddress(&x1, g_x1);
    cudaGetSymbolAddress(&m1, g_m1);

    cudaFuncSetAttribute(attn_mma_kernel, cudaFuncAttributeMaxDynamicSharedMemorySize, SMEM_ATTN);
    cudaFuncSetAttribute(gemm_tc<0, true,  true,  96>,  cudaFuncAttributeMaxDynamicSharedMemorySize, SMEM_GEMM);
    cudaFuncSetAttribute(gemm_tc<1, false, false, 96>,  cudaFuncAttributeMaxDynamicSharedMemorySize, SMEM_GEMM);
    cudaFuncSetAttribute(gemm_tc<2, true,  false, 96>,  cudaFuncAttributeMaxDynamicSharedMemorySize, SMEM_GEMM);
    cudaFuncSetAttribute(gemm_tc<3, false, false, 384>, cudaFuncAttributeMaxDynamicSharedMemorySize, SMEM_GEMM);

    // 0. bias+mask table
    tbl_kernel<<<dim3(392, 24), 256>>>(rel_b);
    // 1. QKV gemm (fused LN1 + roll/partition gather) -> fp16 q/k/v
    gemm_tc<0, true, true, 96><<<dim3(3, TOK / 128), 256, SMEM_GEMM>>>(
        x, qkv_w, qkv_b, norm1_g, norm1_b, nullptr, nullptr);
    // 2. attention (fp16 MMA) -> fp16 owin
    attn_mma_kernel<<<BWIN * HEADS, 256, SMEM_ATTN>>>();
    // 3. proj + window reverse + residual -> fp32 g_x1
    gemm_tc<1, false, false, 96><<<dim3(1, TOK / 128), 256, SMEM_GEMM>>>(
        owin, proj_w, proj_b, nullptr, nullptr, x, nullptr);
    // 4. fc1 (fused LN2) + gelu -> fp16 g_m1
    gemm_tc<2, true, false, 96><<<dim3(4, TOK / 128), 256, SMEM_GEMM>>>(
        x1, fc1_w, fc1_b, norm2_g, norm2_b, nullptr, (float*)m1);
    // 5. fc2 + residual -> fp32 out
    gemm_tc<3, false, false, 384><<<dim3(1, TOK / 128), 256, SMEM_GEMM>>>(
        m1, fc2_w, fc2_b, nullptr, nullptr, nullptr, out);
}